// round 11
// baseline (speedup 1.0000x reference)
#include <cuda_runtime.h>
#include <math.h>

#define FULL 0xffffffffu
typedef unsigned long long ull;

// Problem constants
constexpr int B_ = 4;
constexpr int P_ = 2048;
constexpr int NPOS = B_ * P_;           // 8192
constexpr int NCHUNK = 64;              // 32-position chunks per sequence

// Scratch (device globals; no allocation in kernel_launch)
__device__ float g_enc_psi[NPOS * 32];
__device__ float g_enc[NPOS * 32];
__device__ float g_u[NPOS * 4];
__device__ float g_num[NPOS * 4 * 32];
__device__ float g_den[NPOS * 4];
__device__ float g_ct2[B_ * NCHUNK * 32];       // chunk totals of enc_psi
__device__ float g_ct4n[16 * NCHUNK * 32];      // chunk totals of u*enc per (b,h)
__device__ float g_ct4d[16 * NCHUNK];           // chunk totals of u per (b,h)
__device__ float4 g_w1d[128 * 32];              // rho w1 duplicated (w,w,w',w')
__device__ float4 g_w2d[64 * 32];               // rho w2 duplicated

// ---- f32x2 packed helpers (sm_103a FFMA2 path) ------------------------------
__device__ __forceinline__ ull pack2(float x, float y) {
    ull r; asm("mov.b64 %0, {%1, %2};" : "=l"(r) : "f"(x), "f"(y)); return r;
}
__device__ __forceinline__ void unpack2(ull v, float& x, float& y) {
    asm("mov.b64 {%0, %1}, %2;" : "=f"(x), "=f"(y) : "l"(v));
}
__device__ __forceinline__ ull ffma2(ull a, ull b, ull c) {
    ull d; asm("fma.rn.f32x2 %0, %1, %2, %3;" : "=l"(d) : "l"(a), "l"(b), "l"(c));
    return d;
}

// combined[lane] for one position
__device__ __forceinline__ float combined_lane(float t, float v, int m, int lane) {
    if (lane < 8) {
        float sc;
        switch (lane >> 1) {
            case 0:  sc = 1.0f;   break;
            case 1:  sc = 0.1f;   break;
            case 2:  sc = 0.01f;  break;
            default: sc = 0.001f; break;
        }
        float r = t * sc;
        return (lane & 1) ? cosf(r) : sinf(r);
    } else if (lane == 8) {
        return v;
    } else if (lane < 31) {
        return (m == lane - 8) ? 1.0f : 0.0f;
    }
    return 0.0f;
}

// ---------------------------------------------------------------------------
// K1: features + psi MLP + phi MLP + enc_psi chunk totals.
// Grid 256 (block = one 32-position chunk) x 256 threads; warp = 4 positions.
// ---------------------------------------------------------------------------
__global__ __launch_bounds__(256) void k1_feat_mlps(
    const float* __restrict__ times, const float* __restrict__ values,
    const int* __restrict__ meas, const float* __restrict__ mask,
    const float* __restrict__ pw1, const float* __restrict__ pb1,
    const float* __restrict__ pw2, const float* __restrict__ pb2,
    const float* __restrict__ fw1, const float* __restrict__ fb1,
    const float* __restrict__ fw2, const float* __restrict__ fb2)
{
    __shared__ float4 s_pw1[8 * 32], s_pw2[8 * 32];
    __shared__ float4 s_fw1[8 * 32], s_fw2[8 * 32];
    __shared__ float  s_pb1[32], s_pb2[32], s_fb1[32], s_fb2[32];
    __shared__ float4 s_x4[8][4][8];
    __shared__ float4 s_h4[8][4][8];
    __shared__ float  s_part[8][32];     // per-warp enc_psi partial sums

    int tid = threadIdx.x;
    for (int i = tid; i < 8 * 32; i += 256) {
        int i4 = i >> 5, l = i & 31, r0 = i4 * 4;
        float p3 = (r0 + 3 < 31) ? pw1[(r0 + 3) * 32 + l] : 0.0f;
        float f3 = (r0 + 3 < 31) ? fw1[(r0 + 3) * 32 + l] : 0.0f;
        s_pw1[i] = make_float4(pw1[r0 * 32 + l], pw1[(r0 + 1) * 32 + l],
                               pw1[(r0 + 2) * 32 + l], p3);
        s_fw1[i] = make_float4(fw1[r0 * 32 + l], fw1[(r0 + 1) * 32 + l],
                               fw1[(r0 + 2) * 32 + l], f3);
        s_pw2[i] = make_float4(pw2[r0 * 32 + l], pw2[(r0 + 1) * 32 + l],
                               pw2[(r0 + 2) * 32 + l], pw2[(r0 + 3) * 32 + l]);
        s_fw2[i] = make_float4(fw2[r0 * 32 + l], fw2[(r0 + 1) * 32 + l],
                               fw2[(r0 + 2) * 32 + l], fw2[(r0 + 3) * 32 + l]);
    }
    if (tid < 32) { s_pb1[tid] = pb1[tid]; s_pb2[tid] = pb2[tid];
                    s_fb1[tid] = fb1[tid]; s_fb2[tid] = fb2[tid]; }
    __syncthreads();

    int lane = tid & 31;
    int w    = tid >> 5;
    int pos0 = blockIdx.x * 32 + w * 4;
    int b    = blockIdx.x >> 6;
    int chunk = blockIdx.x & 63;

    float mk[4];
    #pragma unroll
    for (int q = 0; q < 4; q++) {
        int pos = pos0 + q;
        float t = times[pos], v = values[pos];
        mk[q] = mask[pos];
        int m = meas[pos];
        ((float*)&s_x4[w][q])[lane] = combined_lane(t, v, m, lane) * mk[q];
    }
    __syncwarp();

    float acc[4];

    // psi layer 1
    #pragma unroll
    for (int q = 0; q < 4; q++) acc[q] = s_pb1[lane];
    #pragma unroll
    for (int i4 = 0; i4 < 8; i4++) {
        float4 wv = s_pw1[i4 * 32 + lane];
        #pragma unroll
        for (int q = 0; q < 4; q++) {
            float4 xv = s_x4[w][q][i4];
            acc[q] += xv.x * wv.x; acc[q] += xv.y * wv.y;
            acc[q] += xv.z * wv.z; acc[q] += xv.w * wv.w;
        }
    }
    #pragma unroll
    for (int q = 0; q < 4; q++)
        ((float*)&s_h4[w][q])[lane] = fmaxf(acc[q], 0.0f) * mk[q];
    __syncwarp();

    // psi layer 2 (+ chunk partial)
    #pragma unroll
    for (int q = 0; q < 4; q++) acc[q] = s_pb2[lane];
    #pragma unroll
    for (int i4 = 0; i4 < 8; i4++) {
        float4 wv = s_pw2[i4 * 32 + lane];
        #pragma unroll
        for (int q = 0; q < 4; q++) {
            float4 xv = s_h4[w][q][i4];
            acc[q] += xv.x * wv.x; acc[q] += xv.y * wv.y;
            acc[q] += xv.z * wv.z; acc[q] += xv.w * wv.w;
        }
    }
    float psum = 0.0f;
    #pragma unroll
    for (int q = 0; q < 4; q++) {
        float ev = fmaxf(acc[q], 0.0f) * mk[q];
        g_enc_psi[(pos0 + q) * 32 + lane] = ev;
        psum += ev;
    }
    s_part[w][lane] = psum;
    __syncwarp();

    // phi layer 1
    #pragma unroll
    for (int q = 0; q < 4; q++) acc[q] = s_fb1[lane];
    #pragma unroll
    for (int i4 = 0; i4 < 8; i4++) {
        float4 wv = s_fw1[i4 * 32 + lane];
        #pragma unroll
        for (int q = 0; q < 4; q++) {
            float4 xv = s_x4[w][q][i4];
            acc[q] += xv.x * wv.x; acc[q] += xv.y * wv.y;
            acc[q] += xv.z * wv.z; acc[q] += xv.w * wv.w;
        }
    }
    #pragma unroll
    for (int q = 0; q < 4; q++)
        ((float*)&s_h4[w][q])[lane] = fmaxf(acc[q], 0.0f) * mk[q];
    __syncwarp();

    // phi layer 2
    #pragma unroll
    for (int q = 0; q < 4; q++) acc[q] = s_fb2[lane];
    #pragma unroll
    for (int i4 = 0; i4 < 8; i4++) {
        float4 wv = s_fw2[i4 * 32 + lane];
        #pragma unroll
        for (int q = 0; q < 4; q++) {
            float4 xv = s_h4[w][q][i4];
            acc[q] += xv.x * wv.x; acc[q] += xv.y * wv.y;
            acc[q] += xv.z * wv.z; acc[q] += xv.w * wv.w;
        }
    }
    #pragma unroll
    for (int q = 0; q < 4; q++)
        g_enc[(pos0 + q) * 32 + lane] = fmaxf(acc[q], 0.0f) * mk[q];

    // chunk total of enc_psi
    __syncthreads();
    if (w == 0) {
        float t = 0.0f;
        #pragma unroll
        for (int w2 = 0; w2 < 8; w2++) t += s_part[w2][lane];
        g_ct2[(b * NCHUNK + chunk) * 32 + lane] = t;
    }
}

// ---------------------------------------------------------------------------
// K3: inline aggraw (cumsum via g_ct2 chunk offsets + within-chunk prefix),
// agg matvec, keys matvec, preattn, u, and k4 chunk totals (u*enc, u).
// Grid 256 (block = chunk) x 256 threads.
// ---------------------------------------------------------------------------
__global__ __launch_bounds__(256) void k3_preattn(
    const float* __restrict__ times, const float* __restrict__ values,
    const int* __restrict__ meas, const float* __restrict__ mask,
    const float* __restrict__ arw, const float* __restrict__ arb,
    const float* __restrict__ wk, const float* __restrict__ wq)
{
    __shared__ float4 s_ar4[8 * 32];
    __shared__ float4 s_wk4[32 * 32];
    __shared__ float  s_ab[32], s_wq[64];
    __shared__ float4 s_g4[8][4][8];
    __shared__ float2 s_y2[8][4][32];
    __shared__ float  s_wp[8][32];
    __shared__ float  s_pn[8][4][32];
    __shared__ float  s_pd[8][4];

    int tid = threadIdx.x;
    for (int i = tid; i < 8 * 32; i += 256) {
        int i4 = i >> 5, l = i & 31, r0 = i4 * 4;
        s_ar4[i] = make_float4(arw[r0 * 32 + l], arw[(r0 + 1) * 32 + l],
                               arw[(r0 + 2) * 32 + l], arw[(r0 + 3) * 32 + l]);
    }
    for (int i = tid; i < 32 * 32; i += 256) {
        int i2 = i >> 5, l = i & 31, r0 = i2 * 2;
        float w2a = (r0 + 1 < 63) ? wk[(r0 + 1) * 64 + l]      : 0.0f;
        float w2b = (r0 + 1 < 63) ? wk[(r0 + 1) * 64 + l + 32] : 0.0f;
        s_wk4[i] = make_float4(wk[r0 * 64 + l], wk[r0 * 64 + l + 32], w2a, w2b);
    }
    if (tid < 32) s_ab[tid] = arb[tid];
    if (tid < 64) s_wq[tid] = wq[tid];

    int lane  = tid & 31;
    int w     = tid >> 5;
    int b     = blockIdx.x >> 6;
    int chunk = blockIdx.x & 63;
    int pos0  = blockIdx.x * 32 + w * 4;        // global position
    int lp0   = chunk * 32 + w * 4;             // LOCAL (within-sequence) position

    // Stage raw combined; load own-chunk enc_psi; within-warp prefix.
    float mk[4], cq[4];
    {
        float eq[4];
        #pragma unroll
        for (int q = 0; q < 4; q++) {
            int pos = pos0 + q;
            float t = times[pos], v = values[pos];
            mk[q] = mask[pos];
            int m = meas[pos];
            ((float*)s_y2[w][q])[lane] = combined_lane(t, v, m, lane);
            eq[q] = g_enc_psi[pos * 32 + lane];
        }
        cq[0] = eq[0];
        cq[1] = cq[0] + eq[1];
        cq[2] = cq[1] + eq[2];
        cq[3] = cq[2] + eq[3];
        s_wp[w][lane] = cq[3];
    }
    __syncthreads();   // covers weights, s_y2 low, s_wp

    // exclusive offset: preceding chunks (g_ct2) + preceding warps
    float off;
    {
        const float* ct = g_ct2 + (b * NCHUNK) * 32 + lane;
        float o0 = 0.f, o1 = 0.f, o2 = 0.f, o3 = 0.f;
        int k = 0;
        for (; k + 4 <= chunk; k += 4) {
            o0 += ct[k * 32];       o1 += ct[(k + 1) * 32];
            o2 += ct[(k + 2) * 32]; o3 += ct[(k + 3) * 32];
        }
        for (; k < chunk; k++) o0 += ct[k * 32];
        off = (o0 + o1) + (o2 + o3);
    }
    #pragma unroll
    for (int w2 = 0; w2 < 8; w2++)
        if (w2 < w) off += s_wp[w2][lane];

    // aggraw = cumsum / (LOCAL count) * mask -> staged for broadcast matvec
    #pragma unroll
    for (int q = 0; q < 4; q++) {
        float cum = off + cq[q];
        float agr = __fdividef(cum, (float)(lp0 + q + 1)) * mk[q];
        ((float*)&s_g4[w][q])[lane] = agr;
    }
    __syncwarp();

    // agg matvec (32x32)
    float agg[4];
    #pragma unroll
    for (int q = 0; q < 4; q++) agg[q] = s_ab[lane];
    #pragma unroll
    for (int i4 = 0; i4 < 8; i4++) {
        float4 wv = s_ar4[i4 * 32 + lane];
        #pragma unroll
        for (int q = 0; q < 4; q++) {
            float4 xv = s_g4[w][q][i4];
            agg[q] += xv.x * wv.x; agg[q] += xv.y * wv.y;
            agg[q] += xv.z * wv.z; agg[q] += xv.w * wv.w;
        }
    }
    #pragma unroll
    for (int q = 0; q < 4; q++) {
        ((float*)s_y2[w][q])[31 + lane] = agg[q] * mk[q];
        if (lane == 0) ((float*)s_y2[w][q])[63] = 0.0f;
    }
    __syncwarp();

    // keys matvec (63x64)
    float a0[4] = {0.f, 0.f, 0.f, 0.f}, a1[4] = {0.f, 0.f, 0.f, 0.f};
    #pragma unroll
    for (int i2 = 0; i2 < 32; i2++) {
        float4 wv = s_wk4[i2 * 32 + lane];
        #pragma unroll
        for (int q = 0; q < 4; q++) {
            float2 yv = s_y2[w][q][i2];
            a0[q] += yv.x * wv.x; a1[q] += yv.x * wv.y;
            a0[q] += yv.y * wv.z; a1[q] += yv.y * wv.w;
        }
    }

    int hh = lane & 3, dd = lane >> 2;
    float q0 = s_wq[hh * 16 + dd], q1 = s_wq[hh * 16 + dd + 8];
    float ufull[4];
    #pragma unroll
    for (int q = 0; q < 4; q++) {
        float part = a0[q] * mk[q] * q0 + a1[q] * mk[q] * q1;
        part += __shfl_xor_sync(FULL, part, 4);
        part += __shfl_xor_sync(FULL, part, 8);
        part += __shfl_xor_sync(FULL, part, 16);
        float pre = part * 0.25f * mk[q];
        ufull[q] = expf(pre);                    // lane l holds head l&3
        if (lane < 4) g_u[(pos0 + q) * 4 + lane] = ufull[q];
    }

    // k4 chunk totals: pn[h][lane] = sum_q u[q][h]*enc[q][lane]; pd[h] = sum_q u[q][h]
    {
        float e2q[4];
        #pragma unroll
        for (int q = 0; q < 4; q++) e2q[q] = g_enc[(pos0 + q) * 32 + lane];
        #pragma unroll
        for (int h = 0; h < 4; h++) {
            float s = 0.0f;
            #pragma unroll
            for (int q = 0; q < 4; q++)
                s += __shfl_sync(FULL, ufull[q], h) * e2q[q];
            s_pn[w][h][lane] = s;
        }
        if (lane < 4)
            s_pd[w][lane] = ufull[0] + ufull[1] + ufull[2] + ufull[3];
    }
    __syncthreads();

    if (w < 4) {
        int h = w;
        float t = 0.0f;
        #pragma unroll
        for (int w2 = 0; w2 < 8; w2++) t += s_pn[w2][h][lane];
        g_ct4n[((b * 4 + h) * NCHUNK + chunk) * 32 + lane] = t;
        if (lane == 0) {
            float td = 0.0f;
            #pragma unroll
            for (int w2 = 0; w2 < 8; w2++) td += s_pd[w2][h];
            g_ct4d[(b * 4 + h) * NCHUNK + chunk] = td;
        }
    }
}

// ---------------------------------------------------------------------------
// K4b: pure offset + write, PLUS staging of duplicated rho weights for K5.
// One warp per (b,h,chunk) = 1024 warps = 128 blocks x 256 threads.
// ---------------------------------------------------------------------------
__global__ __launch_bounds__(256) void k4_scan(
    const float* __restrict__ rw1, const float* __restrict__ rw2)
{
    int tid  = threadIdx.x;

    // Stage duplicated rho weights (for K5's LDG path): 48 float4 per block.
    if (tid < 48) {
        if (tid < 32) {
            int idx = blockIdx.x * 32 + tid;          // 0..4095
            int k = idx >> 5, l = idx & 31;
            float wa = rw1[k * 64 + l], wb = rw1[k * 64 + l + 32];
            g_w1d[idx] = make_float4(wa, wa, wb, wb);
        } else {
            int idx = blockIdx.x * 16 + (tid - 32);   // 0..2047
            int k = idx >> 5, l = idx & 31;
            float wa = rw2[k * 64 + l], wb = rw2[k * 64 + l + 32];
            g_w2d[idx] = make_float4(wa, wa, wb, wb);
        }
    }

    int lane = tid & 31;
    int w    = tid >> 5;
    int wg   = blockIdx.x * 8 + w;       // 0..1023
    int bh   = wg >> 6;
    int c    = wg & 63;
    int b    = bh >> 2, h = bh & 3;

    // num offset: sum of preceding chunk totals (coalesced)
    float offn;
    {
        const float* ct = g_ct4n + (bh * NCHUNK) * 32 + lane;
        float o0 = 0.f, o1 = 0.f, o2 = 0.f, o3 = 0.f;
        int k = 0;
        for (; k + 4 <= c; k += 4) {
            o0 += ct[k * 32];       o1 += ct[(k + 1) * 32];
            o2 += ct[(k + 2) * 32]; o3 += ct[(k + 3) * 32];
        }
        for (; k < c; k++) o0 += ct[k * 32];
        offn = (o0 + o1) + (o2 + o3);
    }
    // den offset: lanes cover chunk indices, xor-reduce
    float offd;
    {
        const float* cd = g_ct4d + bh * NCHUNK;
        float myd = 0.0f;
        if (lane < c)      myd  = cd[lane];
        if (lane + 32 < c) myd += cd[lane + 32];
        #pragma unroll
        for (int o = 16; o >= 1; o >>= 1) myd += __shfl_xor_sync(FULL, myd, o);
        offd = myd;
    }

    const float* up = g_u   + b * P_ * 4 + h;
    const float* ep = g_enc + b * P_ * 32 + lane;
    int p0 = c * 32;

    float uv[32], vals[32];
    #pragma unroll
    for (int j = 0; j < 32; j++) uv[j] = up[(p0 + j) * 4];
    #pragma unroll
    for (int j = 0; j < 32; j++) vals[j] = uv[j] * ep[(p0 + j) * 32];

    float* nq = g_num + (b * P_ * 4 + h) * 32 + lane;
    float* dq = g_den + b * P_ * 4 + h;

    float accn = offn, accu = offd;
    #pragma unroll
    for (int j = 0; j < 32; j++) {
        int p = p0 + j;
        accn += vals[j];
        accu += uv[j];
        nq[p * 128] = accn;
        if (lane == 0) dq[p * 4] = accu;
    }
}

// ---------------------------------------------------------------------------
// K5 v4: rho MLP, position-pair f32x2, weights via __ldg (L1-resident,
// duplicated layout staged by K4). Only 24KB smem (activations) -> high
// occupancy. Grid 256 x 256 threads (8 warps), warp = 4 positions (2 pairs).
// Inner loop per k: 1 LDG.128(w) + 1 broadcast LDS.128(2 pairs) + 4 FFMA2.
// ---------------------------------------------------------------------------
__global__ __launch_bounds__(256) void k5_rho(
    const float* __restrict__ mask,
    const float* __restrict__ rb1, const float* __restrict__ rb2,
    float* __restrict__ out)
{
    __shared__ ull s_a[8 * 128 * 2];   // [8w][128k][2qp] = 16KB
    __shared__ ull s_h[8 * 64 * 2];    // [8w][64k][2qp]  = 8KB

    int tid = threadIdx.x;
    int w = tid >> 5, lane = tid & 31;

    // Stage activations as position pairs
    int pos0 = (blockIdx.x * 8 + w) * 4;
    float mks[4];
    #pragma unroll
    for (int q = 0; q < 4; q++) mks[q] = mask[pos0 + q];

    #pragma unroll
    for (int qp = 0; qp < 2; qp++) {
        int pa = pos0 + 2 * qp, pb = pa + 1;
        float ma2 = mks[2 * qp] * mks[2 * qp];
        float mb2 = mks[2 * qp + 1] * mks[2 * qp + 1];
        #pragma unroll
        for (int h4 = 0; h4 < 4; h4++) {
            float sa = __fdividef(ma2, g_den[pa * 4 + h4]);
            float sb = __fdividef(mb2, g_den[pb * 4 + h4]);
            float va = g_num[(pa * 4 + h4) * 32 + lane] * sa;
            float vb = g_num[(pb * 4 + h4) * 32 + lane] * sb;
            s_a[(w * 128 + h4 * 32 + lane) * 2 + qp] = pack2(va, vb);
        }
    }
    __syncwarp();

    // ---- layer 1 ----
    ull accA[2], accB[2];
    {
        float b0 = rb1[lane], b1v = rb1[lane + 32];
        ull pA = pack2(b0, b0), pB = pack2(b1v, b1v);
        accA[0] = pA; accA[1] = pA; accB[0] = pB; accB[1] = pB;
    }

    const ulonglong2* w1v = (const ulonglong2*)g_w1d;
    #pragma unroll 8
    for (int k = 0; k < 128; k++) {
        ulonglong2 wv = __ldg(&w1v[k * 32 + lane]);     // (w_l dup, w_l32 dup)
        ulonglong2 a01 = *(const ulonglong2*)(s_a + (w * 128 + k) * 2);  // bcast
        accA[0] = ffma2(a01.x, wv.x, accA[0]); accB[0] = ffma2(a01.x, wv.y, accB[0]);
        accA[1] = ffma2(a01.y, wv.x, accA[1]); accB[1] = ffma2(a01.y, wv.y, accB[1]);
    }

    // relu + mask -> s_h
    #pragma unroll
    for (int qp = 0; qp < 2; qp++) {
        float r0, r1; unpack2(accA[qp], r0, r1);
        r0 = fmaxf(r0, 0.0f) * mks[2 * qp];
        r1 = fmaxf(r1, 0.0f) * mks[2 * qp + 1];
        s_h[(w * 64 + lane) * 2 + qp] = pack2(r0, r1);
        unpack2(accB[qp], r0, r1);
        r0 = fmaxf(r0, 0.0f) * mks[2 * qp];
        r1 = fmaxf(r1, 0.0f) * mks[2 * qp + 1];
        s_h[(w * 64 + lane + 32) * 2 + qp] = pack2(r0, r1);
    }
    __syncwarp();

    // ---- layer 2 ----
    {
        float b0 = rb2[lane], b1v = rb2[lane + 32];
        ull pA = pack2(b0, b0), pB = pack2(b1v, b1v);
        accA[0] = pA; accA[1] = pA; accB[0] = pB; accB[1] = pB;
    }

    const ulonglong2* w2v = (const ulonglong2*)g_w2d;
    #pragma unroll 8
    for (int k = 0; k < 64; k++) {
        ulonglong2 wv = __ldg(&w2v[k * 32 + lane]);
        ulonglong2 a01 = *(const ulonglong2*)(s_h + (w * 64 + k) * 2);   // bcast
        accA[0] = ffma2(a01.x, wv.x, accA[0]); accB[0] = ffma2(a01.x, wv.y, accB[0]);
        accA[1] = ffma2(a01.y, wv.x, accA[1]); accB[1] = ffma2(a01.y, wv.y, accB[1]);
    }

    // relu + mask -> output
    #pragma unroll
    for (int qp = 0; qp < 2; qp++) {
        int pa = pos0 + 2 * qp, pb = pa + 1;
        float r0, r1; unpack2(accA[qp], r0, r1);
        out[pa * 64 + lane] = fmaxf(r0, 0.0f) * mks[2 * qp];
        out[pb * 64 + lane] = fmaxf(r1, 0.0f) * mks[2 * qp + 1];
        unpack2(accB[qp], r0, r1);
        out[pa * 64 + lane + 32] = fmaxf(r0, 0.0f) * mks[2 * qp];
        out[pb * 64 + lane + 32] = fmaxf(r1, 0.0f) * mks[2 * qp + 1];
    }
}

// ---------------------------------------------------------------------------
extern "C" void kernel_launch(void* const* d_in, const int* in_sizes, int n_in,
                              void* d_out, int out_size)
{
    const float* times   = (const float*)d_in[0];
    const float* values  = (const float*)d_in[1];
    const int*   meas    = (const int*)  d_in[2];
    const float* mask    = (const float*)d_in[3];
    const float* psi_w1  = (const float*)d_in[4];
    const float* psi_b1  = (const float*)d_in[5];
    const float* psi_w2  = (const float*)d_in[6];
    const float* psi_b2  = (const float*)d_in[7];
    const float* arho_w  = (const float*)d_in[8];
    const float* arho_b  = (const float*)d_in[9];
    const float* W_k     = (const float*)d_in[10];
    const float* W_q     = (const float*)d_in[11];
    const float* phi_w1  = (const float*)d_in[12];
    const float* phi_b1  = (const float*)d_in[13];
    const float* phi_w2  = (const float*)d_in[14];
    const float* phi_b2  = (const float*)d_in[15];
    const float* rho_w1  = (const float*)d_in[16];
    const float* rho_b1  = (const float*)d_in[17];
    const float* rho_w2  = (const float*)d_in[18];
    const float* rho_b2  = (const float*)d_in[19];
    float* out = (float*)d_out;

    k1_feat_mlps<<<256, 256>>>(times, values, meas, mask,
                               psi_w1, psi_b1, psi_w2, psi_b2,
                               phi_w1, phi_b1, phi_w2, phi_b2);
    k3_preattn<<<256, 256>>>(times, values, meas, mask,
                             arho_w, arho_b, W_k, W_q);
    k4_scan<<<128, 256>>>(rho_w1, rho_w2);
    k5_rho<<<256, 256>>>(mask, rho_b1, rho_b2, out);
}

// round 12
// speedup vs baseline: 1.1950x; 1.1950x over previous
#include <cuda_runtime.h>
#include <math.h>

#define FULL 0xffffffffu
typedef unsigned long long ull;

// Problem constants
constexpr int B_ = 4;
constexpr int P_ = 2048;
constexpr int NPOS = B_ * P_;           // 8192
constexpr int NCHUNK = 64;              // 32-position chunks per sequence

// Scratch (device globals; no allocation in kernel_launch)
__device__ float g_enc_psi[NPOS * 32];
__device__ float g_enc[NPOS * 32];
__device__ float g_u[NPOS * 4];
__device__ float g_num[NPOS * 4 * 32];
__device__ float g_den[NPOS * 4];
__device__ float g_ct2[B_ * NCHUNK * 32];       // chunk totals of enc_psi
__device__ float g_ct4n[16 * NCHUNK * 32];      // chunk totals of u*enc per (b,h)
__device__ float g_ct4d[16 * NCHUNK];           // chunk totals of u per (b,h)

// ---- f32x2 packed helpers (sm_103a FFMA2 path) ------------------------------
__device__ __forceinline__ ull pack2(float x, float y) {
    ull r; asm("mov.b64 %0, {%1, %2};" : "=l"(r) : "f"(x), "f"(y)); return r;
}
__device__ __forceinline__ void unpack2(ull v, float& x, float& y) {
    asm("mov.b64 {%0, %1}, %2;" : "=f"(x), "=f"(y) : "l"(v));
}
__device__ __forceinline__ ull ffma2(ull a, ull b, ull c) {
    ull d; asm("fma.rn.f32x2 %0, %1, %2, %3;" : "=l"(d) : "l"(a), "l"(b), "l"(c));
    return d;
}

// combined[lane] for one position
__device__ __forceinline__ float combined_lane(float t, float v, int m, int lane) {
    if (lane < 8) {
        float sc;
        switch (lane >> 1) {
            case 0:  sc = 1.0f;   break;
            case 1:  sc = 0.1f;   break;
            case 2:  sc = 0.01f;  break;
            default: sc = 0.001f; break;
        }
        float r = t * sc;
        return (lane & 1) ? cosf(r) : sinf(r);
    } else if (lane == 8) {
        return v;
    } else if (lane < 31) {
        return (m == lane - 8) ? 1.0f : 0.0f;
    }
    return 0.0f;
}

// ---------------------------------------------------------------------------
// K1: features + psi MLP + phi MLP + enc_psi chunk totals.
// Grid 256 (block = one 32-position chunk) x 256 threads; warp = 4 positions.
// ---------------------------------------------------------------------------
__global__ __launch_bounds__(256) void k1_feat_mlps(
    const float* __restrict__ times, const float* __restrict__ values,
    const int* __restrict__ meas, const float* __restrict__ mask,
    const float* __restrict__ pw1, const float* __restrict__ pb1,
    const float* __restrict__ pw2, const float* __restrict__ pb2,
    const float* __restrict__ fw1, const float* __restrict__ fb1,
    const float* __restrict__ fw2, const float* __restrict__ fb2)
{
    __shared__ float4 s_pw1[8 * 32], s_pw2[8 * 32];
    __shared__ float4 s_fw1[8 * 32], s_fw2[8 * 32];
    __shared__ float  s_pb1[32], s_pb2[32], s_fb1[32], s_fb2[32];
    __shared__ float4 s_x4[8][4][8];
    __shared__ float4 s_h4[8][4][8];
    __shared__ float  s_part[8][32];     // per-warp enc_psi partial sums

    int tid = threadIdx.x;
    for (int i = tid; i < 8 * 32; i += 256) {
        int i4 = i >> 5, l = i & 31, r0 = i4 * 4;
        float p3 = (r0 + 3 < 31) ? pw1[(r0 + 3) * 32 + l] : 0.0f;
        float f3 = (r0 + 3 < 31) ? fw1[(r0 + 3) * 32 + l] : 0.0f;
        s_pw1[i] = make_float4(pw1[r0 * 32 + l], pw1[(r0 + 1) * 32 + l],
                               pw1[(r0 + 2) * 32 + l], p3);
        s_fw1[i] = make_float4(fw1[r0 * 32 + l], fw1[(r0 + 1) * 32 + l],
                               fw1[(r0 + 2) * 32 + l], f3);
        s_pw2[i] = make_float4(pw2[r0 * 32 + l], pw2[(r0 + 1) * 32 + l],
                               pw2[(r0 + 2) * 32 + l], pw2[(r0 + 3) * 32 + l]);
        s_fw2[i] = make_float4(fw2[r0 * 32 + l], fw2[(r0 + 1) * 32 + l],
                               fw2[(r0 + 2) * 32 + l], fw2[(r0 + 3) * 32 + l]);
    }
    if (tid < 32) { s_pb1[tid] = pb1[tid]; s_pb2[tid] = pb2[tid];
                    s_fb1[tid] = fb1[tid]; s_fb2[tid] = fb2[tid]; }
    __syncthreads();

    int lane = tid & 31;
    int w    = tid >> 5;
    int pos0 = blockIdx.x * 32 + w * 4;
    int b    = blockIdx.x >> 6;
    int chunk = blockIdx.x & 63;

    float mk[4];
    #pragma unroll
    for (int q = 0; q < 4; q++) {
        int pos = pos0 + q;
        float t = times[pos], v = values[pos];
        mk[q] = mask[pos];
        int m = meas[pos];
        ((float*)&s_x4[w][q])[lane] = combined_lane(t, v, m, lane) * mk[q];
    }
    __syncwarp();

    float acc[4];

    // psi layer 1
    #pragma unroll
    for (int q = 0; q < 4; q++) acc[q] = s_pb1[lane];
    #pragma unroll
    for (int i4 = 0; i4 < 8; i4++) {
        float4 wv = s_pw1[i4 * 32 + lane];
        #pragma unroll
        for (int q = 0; q < 4; q++) {
            float4 xv = s_x4[w][q][i4];
            acc[q] += xv.x * wv.x; acc[q] += xv.y * wv.y;
            acc[q] += xv.z * wv.z; acc[q] += xv.w * wv.w;
        }
    }
    #pragma unroll
    for (int q = 0; q < 4; q++)
        ((float*)&s_h4[w][q])[lane] = fmaxf(acc[q], 0.0f) * mk[q];
    __syncwarp();

    // psi layer 2 (+ chunk partial)
    #pragma unroll
    for (int q = 0; q < 4; q++) acc[q] = s_pb2[lane];
    #pragma unroll
    for (int i4 = 0; i4 < 8; i4++) {
        float4 wv = s_pw2[i4 * 32 + lane];
        #pragma unroll
        for (int q = 0; q < 4; q++) {
            float4 xv = s_h4[w][q][i4];
            acc[q] += xv.x * wv.x; acc[q] += xv.y * wv.y;
            acc[q] += xv.z * wv.z; acc[q] += xv.w * wv.w;
        }
    }
    float psum = 0.0f;
    #pragma unroll
    for (int q = 0; q < 4; q++) {
        float ev = fmaxf(acc[q], 0.0f) * mk[q];
        g_enc_psi[(pos0 + q) * 32 + lane] = ev;
        psum += ev;
    }
    s_part[w][lane] = psum;
    __syncwarp();

    // phi layer 1
    #pragma unroll
    for (int q = 0; q < 4; q++) acc[q] = s_fb1[lane];
    #pragma unroll
    for (int i4 = 0; i4 < 8; i4++) {
        float4 wv = s_fw1[i4 * 32 + lane];
        #pragma unroll
        for (int q = 0; q < 4; q++) {
            float4 xv = s_x4[w][q][i4];
            acc[q] += xv.x * wv.x; acc[q] += xv.y * wv.y;
            acc[q] += xv.z * wv.z; acc[q] += xv.w * wv.w;
        }
    }
    #pragma unroll
    for (int q = 0; q < 4; q++)
        ((float*)&s_h4[w][q])[lane] = fmaxf(acc[q], 0.0f) * mk[q];
    __syncwarp();

    // phi layer 2
    #pragma unroll
    for (int q = 0; q < 4; q++) acc[q] = s_fb2[lane];
    #pragma unroll
    for (int i4 = 0; i4 < 8; i4++) {
        float4 wv = s_fw2[i4 * 32 + lane];
        #pragma unroll
        for (int q = 0; q < 4; q++) {
            float4 xv = s_h4[w][q][i4];
            acc[q] += xv.x * wv.x; acc[q] += xv.y * wv.y;
            acc[q] += xv.z * wv.z; acc[q] += xv.w * wv.w;
        }
    }
    #pragma unroll
    for (int q = 0; q < 4; q++)
        g_enc[(pos0 + q) * 32 + lane] = fmaxf(acc[q], 0.0f) * mk[q];

    // chunk total of enc_psi
    __syncthreads();
    if (w == 0) {
        float t = 0.0f;
        #pragma unroll
        for (int w2 = 0; w2 < 8; w2++) t += s_part[w2][lane];
        g_ct2[(b * NCHUNK + chunk) * 32 + lane] = t;
    }
}

// ---------------------------------------------------------------------------
// K3: inline aggraw (cumsum via g_ct2 chunk offsets + within-chunk prefix),
// agg matvec, keys matvec, preattn, u, and k4 chunk totals (u*enc, u).
// Grid 256 (block = chunk) x 256 threads.
// ---------------------------------------------------------------------------
__global__ __launch_bounds__(256) void k3_preattn(
    const float* __restrict__ times, const float* __restrict__ values,
    const int* __restrict__ meas, const float* __restrict__ mask,
    const float* __restrict__ arw, const float* __restrict__ arb,
    const float* __restrict__ wk, const float* __restrict__ wq)
{
    __shared__ float4 s_ar4[8 * 32];
    __shared__ float4 s_wk4[32 * 32];
    __shared__ float  s_ab[32], s_wq[64];
    __shared__ float4 s_g4[8][4][8];
    __shared__ float2 s_y2[8][4][32];
    __shared__ float  s_wp[8][32];
    __shared__ float  s_pn[8][4][32];
    __shared__ float  s_pd[8][4];

    int tid = threadIdx.x;
    for (int i = tid; i < 8 * 32; i += 256) {
        int i4 = i >> 5, l = i & 31, r0 = i4 * 4;
        s_ar4[i] = make_float4(arw[r0 * 32 + l], arw[(r0 + 1) * 32 + l],
                               arw[(r0 + 2) * 32 + l], arw[(r0 + 3) * 32 + l]);
    }
    for (int i = tid; i < 32 * 32; i += 256) {
        int i2 = i >> 5, l = i & 31, r0 = i2 * 2;
        float w2a = (r0 + 1 < 63) ? wk[(r0 + 1) * 64 + l]      : 0.0f;
        float w2b = (r0 + 1 < 63) ? wk[(r0 + 1) * 64 + l + 32] : 0.0f;
        s_wk4[i] = make_float4(wk[r0 * 64 + l], wk[r0 * 64 + l + 32], w2a, w2b);
    }
    if (tid < 32) s_ab[tid] = arb[tid];
    if (tid < 64) s_wq[tid] = wq[tid];

    int lane  = tid & 31;
    int w     = tid >> 5;
    int b     = blockIdx.x >> 6;
    int chunk = blockIdx.x & 63;
    int pos0  = blockIdx.x * 32 + w * 4;        // global position
    int lp0   = chunk * 32 + w * 4;             // LOCAL (within-sequence) position

    // Stage raw combined; load own-chunk enc_psi; within-warp prefix.
    float mk[4], cq[4];
    {
        float eq[4];
        #pragma unroll
        for (int q = 0; q < 4; q++) {
            int pos = pos0 + q;
            float t = times[pos], v = values[pos];
            mk[q] = mask[pos];
            int m = meas[pos];
            ((float*)s_y2[w][q])[lane] = combined_lane(t, v, m, lane);
            eq[q] = g_enc_psi[pos * 32 + lane];
        }
        cq[0] = eq[0];
        cq[1] = cq[0] + eq[1];
        cq[2] = cq[1] + eq[2];
        cq[3] = cq[2] + eq[3];
        s_wp[w][lane] = cq[3];
    }
    __syncthreads();   // covers weights, s_y2 low, s_wp

    // exclusive offset: preceding chunks (g_ct2) + preceding warps
    float off;
    {
        const float* ct = g_ct2 + (b * NCHUNK) * 32 + lane;
        float o0 = 0.f, o1 = 0.f, o2 = 0.f, o3 = 0.f;
        int k = 0;
        for (; k + 4 <= chunk; k += 4) {
            o0 += ct[k * 32];       o1 += ct[(k + 1) * 32];
            o2 += ct[(k + 2) * 32]; o3 += ct[(k + 3) * 32];
        }
        for (; k < chunk; k++) o0 += ct[k * 32];
        off = (o0 + o1) + (o2 + o3);
    }
    #pragma unroll
    for (int w2 = 0; w2 < 8; w2++)
        if (w2 < w) off += s_wp[w2][lane];

    // aggraw = cumsum / (LOCAL count) * mask -> staged for broadcast matvec
    #pragma unroll
    for (int q = 0; q < 4; q++) {
        float cum = off + cq[q];
        float agr = __fdividef(cum, (float)(lp0 + q + 1)) * mk[q];
        ((float*)&s_g4[w][q])[lane] = agr;
    }
    __syncwarp();

    // agg matvec (32x32)
    float agg[4];
    #pragma unroll
    for (int q = 0; q < 4; q++) agg[q] = s_ab[lane];
    #pragma unroll
    for (int i4 = 0; i4 < 8; i4++) {
        float4 wv = s_ar4[i4 * 32 + lane];
        #pragma unroll
        for (int q = 0; q < 4; q++) {
            float4 xv = s_g4[w][q][i4];
            agg[q] += xv.x * wv.x; agg[q] += xv.y * wv.y;
            agg[q] += xv.z * wv.z; agg[q] += xv.w * wv.w;
        }
    }
    #pragma unroll
    for (int q = 0; q < 4; q++) {
        ((float*)s_y2[w][q])[31 + lane] = agg[q] * mk[q];
        if (lane == 0) ((float*)s_y2[w][q])[63] = 0.0f;
    }
    __syncwarp();

    // keys matvec (63x64)
    float a0[4] = {0.f, 0.f, 0.f, 0.f}, a1[4] = {0.f, 0.f, 0.f, 0.f};
    #pragma unroll
    for (int i2 = 0; i2 < 32; i2++) {
        float4 wv = s_wk4[i2 * 32 + lane];
        #pragma unroll
        for (int q = 0; q < 4; q++) {
            float2 yv = s_y2[w][q][i2];
            a0[q] += yv.x * wv.x; a1[q] += yv.x * wv.y;
            a0[q] += yv.y * wv.z; a1[q] += yv.y * wv.w;
        }
    }

    int hh = lane & 3, dd = lane >> 2;
    float q0 = s_wq[hh * 16 + dd], q1 = s_wq[hh * 16 + dd + 8];
    float ufull[4];
    #pragma unroll
    for (int q = 0; q < 4; q++) {
        float part = a0[q] * mk[q] * q0 + a1[q] * mk[q] * q1;
        part += __shfl_xor_sync(FULL, part, 4);
        part += __shfl_xor_sync(FULL, part, 8);
        part += __shfl_xor_sync(FULL, part, 16);
        float pre = part * 0.25f * mk[q];
        ufull[q] = expf(pre);                    // lane l holds head l&3
        if (lane < 4) g_u[(pos0 + q) * 4 + lane] = ufull[q];
    }

    // k4 chunk totals: pn[h][lane] = sum_q u[q][h]*enc[q][lane]; pd[h] = sum_q u[q][h]
    {
        float e2q[4];
        #pragma unroll
        for (int q = 0; q < 4; q++) e2q[q] = g_enc[(pos0 + q) * 32 + lane];
        #pragma unroll
        for (int h = 0; h < 4; h++) {
            float s = 0.0f;
            #pragma unroll
            for (int q = 0; q < 4; q++)
                s += __shfl_sync(FULL, ufull[q], h) * e2q[q];
            s_pn[w][h][lane] = s;
        }
        if (lane < 4)
            s_pd[w][lane] = ufull[0] + ufull[1] + ufull[2] + ufull[3];
    }
    __syncthreads();

    if (w < 4) {
        int h = w;
        float t = 0.0f;
        #pragma unroll
        for (int w2 = 0; w2 < 8; w2++) t += s_pn[w2][h][lane];
        g_ct4n[((b * 4 + h) * NCHUNK + chunk) * 32 + lane] = t;
        if (lane == 0) {
            float td = 0.0f;
            #pragma unroll
            for (int w2 = 0; w2 < 8; w2++) td += s_pd[w2][h];
            g_ct4d[(b * 4 + h) * NCHUNK + chunk] = td;
        }
    }
}

// ---------------------------------------------------------------------------
// K4b: pure offset + write. One warp per (b,h,chunk) = 1024 warps = 128
// blocks x 256 threads. Offset from precomputed chunk totals (balanced,
// coalesced); write pass is a register-only 32-step chain.
// ---------------------------------------------------------------------------
__global__ __launch_bounds__(256) void k4_scan()
{
    int tid  = threadIdx.x;
    int lane = tid & 31;
    int w    = tid >> 5;
    int wg   = blockIdx.x * 8 + w;       // 0..1023
    int bh   = wg >> 6;
    int c    = wg & 63;
    int b    = bh >> 2, h = bh & 3;

    // num offset: sum of preceding chunk totals (coalesced)
    float offn;
    {
        const float* ct = g_ct4n + (bh * NCHUNK) * 32 + lane;
        float o0 = 0.f, o1 = 0.f, o2 = 0.f, o3 = 0.f;
        int k = 0;
        for (; k + 4 <= c; k += 4) {
            o0 += ct[k * 32];       o1 += ct[(k + 1) * 32];
            o2 += ct[(k + 2) * 32]; o3 += ct[(k + 3) * 32];
        }
        for (; k < c; k++) o0 += ct[k * 32];
        offn = (o0 + o1) + (o2 + o3);
    }
    // den offset: lanes cover chunk indices, xor-reduce
    float offd;
    {
        const float* cd = g_ct4d + bh * NCHUNK;
        float myd = 0.0f;
        if (lane < c)      myd  = cd[lane];
        if (lane + 32 < c) myd += cd[lane + 32];
        #pragma unroll
        for (int o = 16; o >= 1; o >>= 1) myd += __shfl_xor_sync(FULL, myd, o);
        offd = myd;
    }

    const float* up = g_u   + b * P_ * 4 + h;
    const float* ep = g_enc + b * P_ * 32 + lane;
    int p0 = c * 32;

    float uv[32], vals[32];
    #pragma unroll
    for (int j = 0; j < 32; j++) uv[j] = up[(p0 + j) * 4];
    #pragma unroll
    for (int j = 0; j < 32; j++) vals[j] = uv[j] * ep[(p0 + j) * 32];

    float* nq = g_num + (b * P_ * 4 + h) * 32 + lane;
    float* dq = g_den + b * P_ * 4 + h;

    float accn = offn, accu = offd;
    #pragma unroll
    for (int j = 0; j < 32; j++) {
        int p = p0 + j;
        accn += vals[j];
        accu += uv[j];
        nq[p * 128] = accn;
        if (lane == 0) dq[p * 4] = accu;
    }
}

// ---------------------------------------------------------------------------
// K5 v5: rho MLP, smem weights NON-duplicated k-pair layout, acc=(o,o+32)
// f32x2 packing, duplicated-activation broadcast loads.
//   s_w1[kp*32+l] = (w1[k][l], w1[k][l+32], w1[k+1][l], w1[k+1][l+32])  32KB
//   s_w2 same for layer 2                                               16KB
//   s_a [8w][4q][128k] = (v,v) dup  (LDS.128 bcast covers 2 k's)        32KB
//   s_h [8w][4q][64]   = (h,h) dup                                      16KB
// 96KB total -> 2 blocks/SM. Grid 256 x 256 (8 warps), warp = 4 positions.
// Per k-pair: 1 LDS.128(w) + 4 bcast LDS.128(a) + 8 FFMA2 = 13 instr/16 MACs.
// ---------------------------------------------------------------------------
__global__ __launch_bounds__(256) void k5_rho(
    const float* __restrict__ mask,
    const float* __restrict__ rw1, const float* __restrict__ rb1,
    const float* __restrict__ rw2, const float* __restrict__ rb2,
    float* __restrict__ out)
{
    extern __shared__ char sm5[];
    float4* s_w1 = (float4*)sm5;                    // 2048 float4 = 32KB
    float4* s_w2 = (float4*)(sm5 + 32768);          // 1024 float4 = 16KB
    ull*    s_a  = (ull*)   (sm5 + 49152);          // 4096 ull    = 32KB
    ull*    s_h  = (ull*)   (sm5 + 81920);          // 2048 ull    = 16KB

    int tid = threadIdx.x;
    int w = tid >> 5, lane = tid & 31;

    // Stage weights (k-pair, non-duplicated)
    for (int i = tid; i < 2048; i += 256) {
        int kp = i >> 5, l = i & 31, k = kp * 2;
        s_w1[i] = make_float4(rw1[k * 64 + l],       rw1[k * 64 + l + 32],
                              rw1[(k + 1) * 64 + l], rw1[(k + 1) * 64 + l + 32]);
    }
    for (int i = tid; i < 1024; i += 256) {
        int kp = i >> 5, l = i & 31, k = kp * 2;
        s_w2[i] = make_float4(rw2[k * 64 + l],       rw2[k * 64 + l + 32],
                              rw2[(k + 1) * 64 + l], rw2[(k + 1) * 64 + l + 32]);
    }

    // Stage activations duplicated (v, v): agg2 = num/den * mask^2
    int pos0 = (blockIdx.x * 8 + w) * 4;
    float mks[4];
    #pragma unroll
    for (int q = 0; q < 4; q++) mks[q] = mask[pos0 + q];

    #pragma unroll
    for (int q = 0; q < 4; q++) {
        int pos = pos0 + q;
        float mk2 = mks[q] * mks[q];
        #pragma unroll
        for (int h4 = 0; h4 < 4; h4++) {
            float sc = __fdividef(mk2, g_den[pos * 4 + h4]);
            float v  = g_num[(pos * 4 + h4) * 32 + lane] * sc;
            s_a[(w * 4 + q) * 128 + h4 * 32 + lane] = pack2(v, v);
        }
    }
    __syncthreads();

    // ---- layer 1: acc[q] = (out[q][lane], out[q][lane+32]) ----
    ull acc[4];
    {
        ull bini = pack2(rb1[lane], rb1[lane + 32]);
        #pragma unroll
        for (int q = 0; q < 4; q++) acc[q] = bini;
    }

    const ulonglong2* w1v = (const ulonglong2*)s_w1;
    #pragma unroll 4
    for (int kp = 0; kp < 64; kp++) {
        ulonglong2 wv = w1v[kp * 32 + lane];   // ((wa_k,wb_k),(wa_k1,wb_k1))
        #pragma unroll
        for (int q = 0; q < 4; q++) {
            // broadcast: ((v_k,v_k),(v_k1,v_k1))
            ulonglong2 a2 = *(const ulonglong2*)(s_a + (w * 4 + q) * 128 + kp * 2);
            acc[q] = ffma2(a2.x, wv.x, acc[q]);
            acc[q] = ffma2(a2.y, wv.y, acc[q]);
        }
    }

    // relu + mask -> s_h duplicated (h,h) for outputs lane and lane+32
    #pragma unroll
    for (int q = 0; q < 4; q++) {
        float r0, r1; unpack2(acc[q], r0, r1);
        r0 = fmaxf(r0, 0.0f) * mks[q];
        r1 = fmaxf(r1, 0.0f) * mks[q];
        s_h[(w * 4 + q) * 64 + lane]      = pack2(r0, r0);
        s_h[(w * 4 + q) * 64 + lane + 32] = pack2(r1, r1);
    }
    __syncwarp();

    // ---- layer 2 ----
    {
        ull bini = pack2(rb2[lane], rb2[lane + 32]);
        #pragma unroll
        for (int q = 0; q < 4; q++) acc[q] = bini;
    }

    const ulonglong2* w2v = (const ulonglong2*)s_w2;
    #pragma unroll 4
    for (int kp = 0; kp < 32; kp++) {
        ulonglong2 wv = w2v[kp * 32 + lane];
        #pragma unroll
        for (int q = 0; q < 4; q++) {
            ulonglong2 a2 = *(const ulonglong2*)(s_h + (w * 4 + q) * 64 + kp * 2);
            acc[q] = ffma2(a2.x, wv.x, acc[q]);
            acc[q] = ffma2(a2.y, wv.y, acc[q]);
        }
    }

    // relu + mask -> output
    #pragma unroll
    for (int q = 0; q < 4; q++) {
        int pos = pos0 + q;
        float r0, r1; unpack2(acc[q], r0, r1);
        out[pos * 64 + lane]      = fmaxf(r0, 0.0f) * mks[q];
        out[pos * 64 + lane + 32] = fmaxf(r1, 0.0f) * mks[q];
    }
}

// ---------------------------------------------------------------------------
extern "C" void kernel_launch(void* const* d_in, const int* in_sizes, int n_in,
                              void* d_out, int out_size)
{
    const float* times   = (const float*)d_in[0];
    const float* values  = (const float*)d_in[1];
    const int*   meas    = (const int*)  d_in[2];
    const float* mask    = (const float*)d_in[3];
    const float* psi_w1  = (const float*)d_in[4];
    const float* psi_b1  = (const float*)d_in[5];
    const float* psi_w2  = (const float*)d_in[6];
    const float* psi_b2  = (const float*)d_in[7];
    const float* arho_w  = (const float*)d_in[8];
    const float* arho_b  = (const float*)d_in[9];
    const float* W_k     = (const float*)d_in[10];
    const float* W_q     = (const float*)d_in[11];
    const float* phi_w1  = (const float*)d_in[12];
    const float* phi_b1  = (const float*)d_in[13];
    const float* phi_w2  = (const float*)d_in[14];
    const float* phi_b2  = (const float*)d_in[15];
    const float* rho_w1  = (const float*)d_in[16];
    const float* rho_b1  = (const float*)d_in[17];
    const float* rho_w2  = (const float*)d_in[18];
    const float* rho_b2  = (const float*)d_in[19];
    float* out = (float*)d_out;

    cudaFuncSetAttribute(k5_rho, cudaFuncAttributeMaxDynamicSharedMemorySize, 98304);

    k1_feat_mlps<<<256, 256>>>(times, values, meas, mask,
                               psi_w1, psi_b1, psi_w2, psi_b2,
                               phi_w1, phi_b1, phi_w2, phi_b2);
    k3_preattn<<<256, 256>>>(times, values, meas, mask,
                             arho_w, arho_b, W_k, W_q);
    k4_scan<<<128, 256>>>();
    k5_rho<<<256, 256, 98304>>>(mask, rho_w1, rho_b1, rho_w2, rho_b2, out);
}

// round 13
// speedup vs baseline: 1.2658x; 1.0592x over previous
#include <cuda_runtime.h>
#include <math.h>

#define FULL 0xffffffffu
typedef unsigned long long ull;

// Problem constants
constexpr int B_ = 4;
constexpr int P_ = 2048;
constexpr int NPOS = B_ * P_;           // 8192
constexpr int NCHUNK = 64;              // 32-position chunks per sequence

// Scratch (device globals; no allocation in kernel_launch)
__device__ float g_enc_psi[NPOS * 32];
__device__ float g_enc[NPOS * 32];
__device__ float g_u[NPOS * 4];
__device__ float g_num[NPOS * 4 * 32];
__device__ float g_den[NPOS * 4];
__device__ float g_ct2[B_ * NCHUNK * 32];       // chunk totals of enc_psi
__device__ float g_ct4n[16 * NCHUNK * 32];      // chunk totals of u*enc per (b,h)
__device__ float g_ct4d[16 * NCHUNK];           // chunk totals of u per (b,h)

// combined[lane] for one position
__device__ __forceinline__ float combined_lane(float t, float v, int m, int lane) {
    if (lane < 8) {
        float sc;
        switch (lane >> 1) {
            case 0:  sc = 1.0f;   break;
            case 1:  sc = 0.1f;   break;
            case 2:  sc = 0.01f;  break;
            default: sc = 0.001f; break;
        }
        float r = t * sc;
        return (lane & 1) ? cosf(r) : sinf(r);
    } else if (lane == 8) {
        return v;
    } else if (lane < 31) {
        return (m == lane - 8) ? 1.0f : 0.0f;
    }
    return 0.0f;
}

// ---------------------------------------------------------------------------
// K1: features + psi MLP + phi MLP + enc_psi chunk totals.
// Grid 256 (block = one 32-position chunk) x 256 threads; warp = 4 positions.
// ---------------------------------------------------------------------------
__global__ __launch_bounds__(256) void k1_feat_mlps(
    const float* __restrict__ times, const float* __restrict__ values,
    const int* __restrict__ meas, const float* __restrict__ mask,
    const float* __restrict__ pw1, const float* __restrict__ pb1,
    const float* __restrict__ pw2, const float* __restrict__ pb2,
    const float* __restrict__ fw1, const float* __restrict__ fb1,
    const float* __restrict__ fw2, const float* __restrict__ fb2)
{
    __shared__ float4 s_pw1[8 * 32], s_pw2[8 * 32];
    __shared__ float4 s_fw1[8 * 32], s_fw2[8 * 32];
    __shared__ float  s_pb1[32], s_pb2[32], s_fb1[32], s_fb2[32];
    __shared__ float4 s_x4[8][4][8];
    __shared__ float4 s_h4[8][4][8];
    __shared__ float  s_part[8][32];     // per-warp enc_psi partial sums

    int tid = threadIdx.x;
    for (int i = tid; i < 8 * 32; i += 256) {
        int i4 = i >> 5, l = i & 31, r0 = i4 * 4;
        float p3 = (r0 + 3 < 31) ? pw1[(r0 + 3) * 32 + l] : 0.0f;
        float f3 = (r0 + 3 < 31) ? fw1[(r0 + 3) * 32 + l] : 0.0f;
        s_pw1[i] = make_float4(pw1[r0 * 32 + l], pw1[(r0 + 1) * 32 + l],
                               pw1[(r0 + 2) * 32 + l], p3);
        s_fw1[i] = make_float4(fw1[r0 * 32 + l], fw1[(r0 + 1) * 32 + l],
                               fw1[(r0 + 2) * 32 + l], f3);
        s_pw2[i] = make_float4(pw2[r0 * 32 + l], pw2[(r0 + 1) * 32 + l],
                               pw2[(r0 + 2) * 32 + l], pw2[(r0 + 3) * 32 + l]);
        s_fw2[i] = make_float4(fw2[r0 * 32 + l], fw2[(r0 + 1) * 32 + l],
                               fw2[(r0 + 2) * 32 + l], fw2[(r0 + 3) * 32 + l]);
    }
    if (tid < 32) { s_pb1[tid] = pb1[tid]; s_pb2[tid] = pb2[tid];
                    s_fb1[tid] = fb1[tid]; s_fb2[tid] = fb2[tid]; }
    __syncthreads();

    int lane = tid & 31;
    int w    = tid >> 5;
    int pos0 = blockIdx.x * 32 + w * 4;
    int b    = blockIdx.x >> 6;
    int chunk = blockIdx.x & 63;

    float mk[4];
    #pragma unroll
    for (int q = 0; q < 4; q++) {
        int pos = pos0 + q;
        float t = times[pos], v = values[pos];
        mk[q] = mask[pos];
        int m = meas[pos];
        ((float*)&s_x4[w][q])[lane] = combined_lane(t, v, m, lane) * mk[q];
    }
    __syncwarp();

    float acc[4];

    // psi layer 1
    #pragma unroll
    for (int q = 0; q < 4; q++) acc[q] = s_pb1[lane];
    #pragma unroll
    for (int i4 = 0; i4 < 8; i4++) {
        float4 wv = s_pw1[i4 * 32 + lane];
        #pragma unroll
        for (int q = 0; q < 4; q++) {
            float4 xv = s_x4[w][q][i4];
            acc[q] += xv.x * wv.x; acc[q] += xv.y * wv.y;
            acc[q] += xv.z * wv.z; acc[q] += xv.w * wv.w;
        }
    }
    #pragma unroll
    for (int q = 0; q < 4; q++)
        ((float*)&s_h4[w][q])[lane] = fmaxf(acc[q], 0.0f) * mk[q];
    __syncwarp();

    // psi layer 2 (+ chunk partial)
    #pragma unroll
    for (int q = 0; q < 4; q++) acc[q] = s_pb2[lane];
    #pragma unroll
    for (int i4 = 0; i4 < 8; i4++) {
        float4 wv = s_pw2[i4 * 32 + lane];
        #pragma unroll
        for (int q = 0; q < 4; q++) {
            float4 xv = s_h4[w][q][i4];
            acc[q] += xv.x * wv.x; acc[q] += xv.y * wv.y;
            acc[q] += xv.z * wv.z; acc[q] += xv.w * wv.w;
        }
    }
    float psum = 0.0f;
    #pragma unroll
    for (int q = 0; q < 4; q++) {
        float ev = fmaxf(acc[q], 0.0f) * mk[q];
        g_enc_psi[(pos0 + q) * 32 + lane] = ev;
        psum += ev;
    }
    s_part[w][lane] = psum;
    __syncwarp();

    // phi layer 1
    #pragma unroll
    for (int q = 0; q < 4; q++) acc[q] = s_fb1[lane];
    #pragma unroll
    for (int i4 = 0; i4 < 8; i4++) {
        float4 wv = s_fw1[i4 * 32 + lane];
        #pragma unroll
        for (int q = 0; q < 4; q++) {
            float4 xv = s_x4[w][q][i4];
            acc[q] += xv.x * wv.x; acc[q] += xv.y * wv.y;
            acc[q] += xv.z * wv.z; acc[q] += xv.w * wv.w;
        }
    }
    #pragma unroll
    for (int q = 0; q < 4; q++)
        ((float*)&s_h4[w][q])[lane] = fmaxf(acc[q], 0.0f) * mk[q];
    __syncwarp();

    // phi layer 2
    #pragma unroll
    for (int q = 0; q < 4; q++) acc[q] = s_fb2[lane];
    #pragma unroll
    for (int i4 = 0; i4 < 8; i4++) {
        float4 wv = s_fw2[i4 * 32 + lane];
        #pragma unroll
        for (int q = 0; q < 4; q++) {
            float4 xv = s_h4[w][q][i4];
            acc[q] += xv.x * wv.x; acc[q] += xv.y * wv.y;
            acc[q] += xv.z * wv.z; acc[q] += xv.w * wv.w;
        }
    }
    #pragma unroll
    for (int q = 0; q < 4; q++)
        g_enc[(pos0 + q) * 32 + lane] = fmaxf(acc[q], 0.0f) * mk[q];

    // chunk total of enc_psi
    __syncthreads();
    if (w == 0) {
        float t = 0.0f;
        #pragma unroll
        for (int w2 = 0; w2 < 8; w2++) t += s_part[w2][lane];
        g_ct2[(b * NCHUNK + chunk) * 32 + lane] = t;
    }
}

// ---------------------------------------------------------------------------
// K3: inline aggraw (cumsum via g_ct2 chunk offsets + within-chunk prefix),
// agg matvec, keys matvec, preattn, u, and k4 chunk totals (u*enc, u).
// Grid 256 (block = chunk) x 256 threads.
// ---------------------------------------------------------------------------
__global__ __launch_bounds__(256) void k3_preattn(
    const float* __restrict__ times, const float* __restrict__ values,
    const int* __restrict__ meas, const float* __restrict__ mask,
    const float* __restrict__ arw, const float* __restrict__ arb,
    const float* __restrict__ wk, const float* __restrict__ wq)
{
    __shared__ float4 s_ar4[8 * 32];
    __shared__ float4 s_wk4[32 * 32];
    __shared__ float  s_ab[32], s_wq[64];
    __shared__ float4 s_g4[8][4][8];
    __shared__ float2 s_y2[8][4][32];
    __shared__ float  s_wp[8][32];
    __shared__ float  s_pn[8][4][32];
    __shared__ float  s_pd[8][4];

    int tid = threadIdx.x;
    for (int i = tid; i < 8 * 32; i += 256) {
        int i4 = i >> 5, l = i & 31, r0 = i4 * 4;
        s_ar4[i] = make_float4(arw[r0 * 32 + l], arw[(r0 + 1) * 32 + l],
                               arw[(r0 + 2) * 32 + l], arw[(r0 + 3) * 32 + l]);
    }
    for (int i = tid; i < 32 * 32; i += 256) {
        int i2 = i >> 5, l = i & 31, r0 = i2 * 2;
        float w2a = (r0 + 1 < 63) ? wk[(r0 + 1) * 64 + l]      : 0.0f;
        float w2b = (r0 + 1 < 63) ? wk[(r0 + 1) * 64 + l + 32] : 0.0f;
        s_wk4[i] = make_float4(wk[r0 * 64 + l], wk[r0 * 64 + l + 32], w2a, w2b);
    }
    if (tid < 32) s_ab[tid] = arb[tid];
    if (tid < 64) s_wq[tid] = wq[tid];

    int lane  = tid & 31;
    int w     = tid >> 5;
    int b     = blockIdx.x >> 6;
    int chunk = blockIdx.x & 63;
    int pos0  = blockIdx.x * 32 + w * 4;        // global position
    int lp0   = chunk * 32 + w * 4;             // LOCAL (within-sequence) position

    // Stage raw combined; load own-chunk enc_psi; within-warp prefix.
    float mk[4], cq[4];
    {
        float eq[4];
        #pragma unroll
        for (int q = 0; q < 4; q++) {
            int pos = pos0 + q;
            float t = times[pos], v = values[pos];
            mk[q] = mask[pos];
            int m = meas[pos];
            ((float*)s_y2[w][q])[lane] = combined_lane(t, v, m, lane);
            eq[q] = g_enc_psi[pos * 32 + lane];
        }
        cq[0] = eq[0];
        cq[1] = cq[0] + eq[1];
        cq[2] = cq[1] + eq[2];
        cq[3] = cq[2] + eq[3];
        s_wp[w][lane] = cq[3];
    }
    __syncthreads();   // covers weights, s_y2 low, s_wp

    // exclusive offset: preceding chunks (g_ct2) + preceding warps
    float off;
    {
        const float* ct = g_ct2 + (b * NCHUNK) * 32 + lane;
        float o0 = 0.f, o1 = 0.f, o2 = 0.f, o3 = 0.f;
        int k = 0;
        for (; k + 4 <= chunk; k += 4) {
            o0 += ct[k * 32];       o1 += ct[(k + 1) * 32];
            o2 += ct[(k + 2) * 32]; o3 += ct[(k + 3) * 32];
        }
        for (; k < chunk; k++) o0 += ct[k * 32];
        off = (o0 + o1) + (o2 + o3);
    }
    #pragma unroll
    for (int w2 = 0; w2 < 8; w2++)
        if (w2 < w) off += s_wp[w2][lane];

    // aggraw = cumsum / (LOCAL count) * mask -> staged for broadcast matvec
    #pragma unroll
    for (int q = 0; q < 4; q++) {
        float cum = off + cq[q];
        float agr = __fdividef(cum, (float)(lp0 + q + 1)) * mk[q];
        ((float*)&s_g4[w][q])[lane] = agr;
    }
    __syncwarp();

    // agg matvec (32x32)
    float agg[4];
    #pragma unroll
    for (int q = 0; q < 4; q++) agg[q] = s_ab[lane];
    #pragma unroll
    for (int i4 = 0; i4 < 8; i4++) {
        float4 wv = s_ar4[i4 * 32 + lane];
        #pragma unroll
        for (int q = 0; q < 4; q++) {
            float4 xv = s_g4[w][q][i4];
            agg[q] += xv.x * wv.x; agg[q] += xv.y * wv.y;
            agg[q] += xv.z * wv.z; agg[q] += xv.w * wv.w;
        }
    }
    #pragma unroll
    for (int q = 0; q < 4; q++) {
        ((float*)s_y2[w][q])[31 + lane] = agg[q] * mk[q];
        if (lane == 0) ((float*)s_y2[w][q])[63] = 0.0f;
    }
    __syncwarp();

    // keys matvec (63x64)
    float a0[4] = {0.f, 0.f, 0.f, 0.f}, a1[4] = {0.f, 0.f, 0.f, 0.f};
    #pragma unroll
    for (int i2 = 0; i2 < 32; i2++) {
        float4 wv = s_wk4[i2 * 32 + lane];
        #pragma unroll
        for (int q = 0; q < 4; q++) {
            float2 yv = s_y2[w][q][i2];
            a0[q] += yv.x * wv.x; a1[q] += yv.x * wv.y;
            a0[q] += yv.y * wv.z; a1[q] += yv.y * wv.w;
        }
    }

    int hh = lane & 3, dd = lane >> 2;
    float q0 = s_wq[hh * 16 + dd], q1 = s_wq[hh * 16 + dd + 8];
    float ufull[4];
    #pragma unroll
    for (int q = 0; q < 4; q++) {
        float part = a0[q] * mk[q] * q0 + a1[q] * mk[q] * q1;
        part += __shfl_xor_sync(FULL, part, 4);
        part += __shfl_xor_sync(FULL, part, 8);
        part += __shfl_xor_sync(FULL, part, 16);
        float pre = part * 0.25f * mk[q];
        ufull[q] = expf(pre);                    // lane l holds head l&3
        if (lane < 4) g_u[(pos0 + q) * 4 + lane] = ufull[q];
    }

    // k4 chunk totals: pn[h][lane] = sum_q u[q][h]*enc[q][lane]; pd[h] = sum_q u[q][h]
    {
        float e2q[4];
        #pragma unroll
        for (int q = 0; q < 4; q++) e2q[q] = g_enc[(pos0 + q) * 32 + lane];
        #pragma unroll
        for (int h = 0; h < 4; h++) {
            float s = 0.0f;
            #pragma unroll
            for (int q = 0; q < 4; q++)
                s += __shfl_sync(FULL, ufull[q], h) * e2q[q];
            s_pn[w][h][lane] = s;
        }
        if (lane < 4)
            s_pd[w][lane] = ufull[0] + ufull[1] + ufull[2] + ufull[3];
    }
    __syncthreads();

    if (w < 4) {
        int h = w;
        float t = 0.0f;
        #pragma unroll
        for (int w2 = 0; w2 < 8; w2++) t += s_pn[w2][h][lane];
        g_ct4n[((b * 4 + h) * NCHUNK + chunk) * 32 + lane] = t;
        if (lane == 0) {
            float td = 0.0f;
            #pragma unroll
            for (int w2 = 0; w2 < 8; w2++) td += s_pd[w2][h];
            g_ct4d[(b * 4 + h) * NCHUNK + chunk] = td;
        }
    }
}

// ---------------------------------------------------------------------------
// K4b: pure offset + write. One warp per (b,h,chunk) = 1024 warps = 128
// blocks x 256 threads. Offset from precomputed chunk totals (balanced,
// coalesced); write pass is a register-only 32-step chain.
// ---------------------------------------------------------------------------
__global__ __launch_bounds__(256) void k4_scan()
{
    int tid  = threadIdx.x;
    int lane = tid & 31;
    int w    = tid >> 5;
    int wg   = blockIdx.x * 8 + w;       // 0..1023
    int bh   = wg >> 6;
    int c    = wg & 63;
    int b    = bh >> 2, h = bh & 3;

    // num offset: sum of preceding chunk totals (coalesced)
    float offn;
    {
        const float* ct = g_ct4n + (bh * NCHUNK) * 32 + lane;
        float o0 = 0.f, o1 = 0.f, o2 = 0.f, o3 = 0.f;
        int k = 0;
        for (; k + 4 <= c; k += 4) {
            o0 += ct[k * 32];       o1 += ct[(k + 1) * 32];
            o2 += ct[(k + 2) * 32]; o3 += ct[(k + 3) * 32];
        }
        for (; k < c; k++) o0 += ct[k * 32];
        offn = (o0 + o1) + (o2 + o3);
    }
    // den offset: lanes cover chunk indices, xor-reduce
    float offd;
    {
        const float* cd = g_ct4d + bh * NCHUNK;
        float myd = 0.0f;
        if (lane < c)      myd  = cd[lane];
        if (lane + 32 < c) myd += cd[lane + 32];
        #pragma unroll
        for (int o = 16; o >= 1; o >>= 1) myd += __shfl_xor_sync(FULL, myd, o);
        offd = myd;
    }

    const float* up = g_u   + b * P_ * 4 + h;
    const float* ep = g_enc + b * P_ * 32 + lane;
    int p0 = c * 32;

    float uv[32], vals[32];
    #pragma unroll
    for (int j = 0; j < 32; j++) uv[j] = up[(p0 + j) * 4];
    #pragma unroll
    for (int j = 0; j < 32; j++) vals[j] = uv[j] * ep[(p0 + j) * 32];

    float* nq = g_num + (b * P_ * 4 + h) * 32 + lane;
    float* dq = g_den + b * P_ * 4 + h;

    float accn = offn, accu = offd;
    #pragma unroll
    for (int j = 0; j < 32; j++) {
        int p = p0 + j;
        accn += vals[j];
        accu += uv[j];
        nq[p * 128] = accn;
        if (lane == 0) dq[p * 4] = accu;
    }
}

// ---------------------------------------------------------------------------
// K5 v6: rho MLP, scalar FFMA, minimal LDS instruction count.
//   Weights: per-lane float4 k-pair layout (128 values / LDS.128):
//     s_w1[kp*32+l] = (W1[k][l], W1[k][l+32], W1[k+1][l], W1[k+1][l+32])
//   Activations: NON-duplicated float4 (4 k's per broadcast LDS.128):
//     s_a4[(w*4+q)*32 + g] = (a[4g], a[4g+1], a[4g+2], a[4g+3])
//   Per 4-k group: 2 wLDS + 4 aLDS (Q=4) + 32 FFMA. 288 LDS/warp total
//   (vs 480 in R11). 72KB smem -> up to 3 blocks/SM. Grid 256 x 256.
// ---------------------------------------------------------------------------
__global__ __launch_bounds__(256) void k5_rho(
    const float* __restrict__ mask,
    const float* __restrict__ rw1, const float* __restrict__ rb1,
    const float* __restrict__ rw2, const float* __restrict__ rb2,
    float* __restrict__ out)
{
    extern __shared__ char sm5[];
    float4* s_w1 = (float4*)sm5;                    // 2048 float4 = 32KB
    float4* s_w2 = (float4*)(sm5 + 32768);          // 1024 float4 = 16KB
    float4* s_a4 = (float4*)(sm5 + 49152);          // 1024 float4 = 16KB
    float*  s_h  = (float*) (sm5 + 65536);          // 2048 float  = 8KB

    int tid = threadIdx.x;
    int w = tid >> 5, lane = tid & 31;

    // Stage weights (k-pair, per-lane distinct: 128 values per LDS/STS.128)
    for (int i = tid; i < 2048; i += 256) {
        int kp = i >> 5, l = i & 31, k = kp * 2;
        s_w1[i] = make_float4(rw1[k * 64 + l],       rw1[k * 64 + l + 32],
                              rw1[(k + 1) * 64 + l], rw1[(k + 1) * 64 + l + 32]);
    }
    for (int i = tid; i < 1024; i += 256) {
        int kp = i >> 5, l = i & 31, k = kp * 2;
        s_w2[i] = make_float4(rw2[k * 64 + l],       rw2[k * 64 + l + 32],
                              rw2[(k + 1) * 64 + l], rw2[(k + 1) * 64 + l + 32]);
    }

    // Stage activations non-duplicated: lane g covers a[4g..4g+3].
    // a[j] = num[pos][h][c] * mask^2 / den[pos][h], j = h*32+c; j = 4*lane + t
    // => h = lane>>3, c = (lane&7)*4 + t  (float4-aligned gmem load).
    int pos0 = (blockIdx.x * 8 + w) * 4;
    float mks[4];
    #pragma unroll
    for (int q = 0; q < 4; q++) mks[q] = mask[pos0 + q];

    {
        int h = lane >> 3;
        int cb = (lane & 7) * 4;
        #pragma unroll
        for (int q = 0; q < 4; q++) {
            int pos = pos0 + q;
            float mk2 = mks[q] * mks[q];
            float sc  = __fdividef(mk2, g_den[pos * 4 + h]);
            float4 nv = *(const float4*)(g_num + (pos * 4 + h) * 32 + cb);
            s_a4[(w * 4 + q) * 32 + lane] =
                make_float4(nv.x * sc, nv.y * sc, nv.z * sc, nv.w * sc);
        }
    }
    __syncthreads();

    // ---- layer 1: acc0 = out[lane], acc1 = out[lane+32] ----
    float acc0[4], acc1[4];
    {
        float b0 = rb1[lane], b1v = rb1[lane + 32];
        #pragma unroll
        for (int q = 0; q < 4; q++) { acc0[q] = b0; acc1[q] = b1v; }
    }

    #pragma unroll 4
    for (int g = 0; g < 32; g++) {                   // 4 k's per group
        float4 wa = s_w1[(2 * g) * 32 + lane];       // k=4g, 4g+1
        float4 wb = s_w1[(2 * g + 1) * 32 + lane];   // k=4g+2, 4g+3
        #pragma unroll
        for (int q = 0; q < 4; q++) {
            float4 av = s_a4[(w * 4 + q) * 32 + g];  // broadcast
            acc0[q] += av.x * wa.x; acc1[q] += av.x * wa.y;
            acc0[q] += av.y * wa.z; acc1[q] += av.y * wa.w;
            acc0[q] += av.z * wb.x; acc1[q] += av.z * wb.y;
            acc0[q] += av.w * wb.z; acc1[q] += av.w * wb.w;
        }
    }

    // relu + mask -> s_h (contiguous floats per q)
    #pragma unroll
    for (int q = 0; q < 4; q++) {
        float* hp = s_h + (w * 4 + q) * 64;
        hp[lane]      = fmaxf(acc0[q], 0.0f) * mks[q];
        hp[lane + 32] = fmaxf(acc1[q], 0.0f) * mks[q];
    }
    __syncwarp();

    // ---- layer 2 ----
    {
        float b0 = rb2[lane], b1v = rb2[lane + 32];
        #pragma unroll
        for (int q = 0; q < 4; q++) { acc0[q] = b0; acc1[q] = b1v; }
    }

    #pragma unroll 4
    for (int g = 0; g < 16; g++) {
        float4 wa = s_w2[(2 * g) * 32 + lane];
        float4 wb = s_w2[(2 * g + 1) * 32 + lane];
        #pragma unroll
        for (int q = 0; q < 4; q++) {
            float4 av = *(const float4*)(s_h + (w * 4 + q) * 64 + 4 * g);  // bcast
            acc0[q] += av.x * wa.x; acc1[q] += av.x * wa.y;
            acc0[q] += av.y * wa.z; acc1[q] += av.y * wa.w;
            acc0[q] += av.z * wb.x; acc1[q] += av.z * wb.y;
            acc0[q] += av.w * wb.z; acc1[q] += av.w * wb.w;
        }
    }

    // relu + mask -> output
    #pragma unroll
    for (int q = 0; q < 4; q++) {
        int pos = pos0 + q;
        out[pos * 64 + lane]      = fmaxf(acc0[q], 0.0f) * mks[q];
        out[pos * 64 + lane + 32] = fmaxf(acc1[q], 0.0f) * mks[q];
    }
}

// ---------------------------------------------------------------------------
extern "C" void kernel_launch(void* const* d_in, const int* in_sizes, int n_in,
                              void* d_out, int out_size)
{
    const float* times   = (const float*)d_in[0];
    const float* values  = (const float*)d_in[1];
    const int*   meas    = (const int*)  d_in[2];
    const float* mask    = (const float*)d_in[3];
    const float* psi_w1  = (const float*)d_in[4];
    const float* psi_b1  = (const float*)d_in[5];
    const float* psi_w2  = (const float*)d_in[6];
    const float* psi_b2  = (const float*)d_in[7];
    const float* arho_w  = (const float*)d_in[8];
    const float* arho_b  = (const float*)d_in[9];
    const float* W_k     = (const float*)d_in[10];
    const float* W_q     = (const float*)d_in[11];
    const float* phi_w1  = (const float*)d_in[12];
    const float* phi_b1  = (const float*)d_in[13];
    const float* phi_w2  = (const float*)d_in[14];
    const float* phi_b2  = (const float*)d_in[15];
    const float* rho_w1  = (const float*)d_in[16];
    const float* rho_b1  = (const float*)d_in[17];
    const float* rho_w2  = (const float*)d_in[18];
    const float* rho_b2  = (const float*)d_in[19];
    float* out = (float*)d_out;

    cudaFuncSetAttribute(k5_rho, cudaFuncAttributeMaxDynamicSharedMemorySize, 73728);

    k1_feat_mlps<<<256, 256>>>(times, values, meas, mask,
                               psi_w1, psi_b1, psi_w2, psi_b2,
                               phi_w1, phi_b1, phi_w2, phi_b2);
    k3_preattn<<<256, 256>>>(times, values, meas, mask,
                             arho_w, arho_b, W_k, W_q);
    k4_scan<<<128, 256>>>();
    k5_rho<<<256, 256, 73728>>>(mask, rho_w1, rho_b1, rho_w2, rho_b2, out);
}

// round 14
// speedup vs baseline: 1.3107x; 1.0355x over previous
#include <cuda_runtime.h>
#include <math.h>

#define FULL 0xffffffffu

// Problem constants
constexpr int B_ = 4;
constexpr int P_ = 2048;
constexpr int NPOS = B_ * P_;           // 8192
constexpr int NCHUNK = 64;              // 32-position chunks per sequence

// Scratch (device globals; no allocation in kernel_launch)
__device__ float g_enc_psi[NPOS * 32];
__device__ float g_enc[NPOS * 32];
__device__ float g_u[NPOS * 4];
__device__ float g_ct2[B_ * NCHUNK * 32];       // chunk totals of enc_psi
__device__ float g_ct4n[16 * NCHUNK * 32];      // chunk totals of u*enc per (b,h)
__device__ float g_ct4d[16 * NCHUNK];           // chunk totals of u per (b,h)

// combined[lane] for one position
__device__ __forceinline__ float combined_lane(float t, float v, int m, int lane) {
    if (lane < 8) {
        float sc;
        switch (lane >> 1) {
            case 0:  sc = 1.0f;   break;
            case 1:  sc = 0.1f;   break;
            case 2:  sc = 0.01f;  break;
            default: sc = 0.001f; break;
        }
        float r = t * sc;
        return (lane & 1) ? cosf(r) : sinf(r);
    } else if (lane == 8) {
        return v;
    } else if (lane < 31) {
        return (m == lane - 8) ? 1.0f : 0.0f;
    }
    return 0.0f;
}

// ---------------------------------------------------------------------------
// K1: features + psi MLP + phi MLP + enc_psi chunk totals.
// Grid 256 (block = one 32-position chunk) x 256 threads; warp = 4 positions.
// ---------------------------------------------------------------------------
__global__ __launch_bounds__(256) void k1_feat_mlps(
    const float* __restrict__ times, const float* __restrict__ values,
    const int* __restrict__ meas, const float* __restrict__ mask,
    const float* __restrict__ pw1, const float* __restrict__ pb1,
    const float* __restrict__ pw2, const float* __restrict__ pb2,
    const float* __restrict__ fw1, const float* __restrict__ fb1,
    const float* __restrict__ fw2, const float* __restrict__ fb2)
{
    __shared__ float4 s_pw1[8 * 32], s_pw2[8 * 32];
    __shared__ float4 s_fw1[8 * 32], s_fw2[8 * 32];
    __shared__ float  s_pb1[32], s_pb2[32], s_fb1[32], s_fb2[32];
    __shared__ float4 s_x4[8][4][8];
    __shared__ float4 s_h4[8][4][8];
    __shared__ float  s_part[8][32];     // per-warp enc_psi partial sums

    int tid = threadIdx.x;
    for (int i = tid; i < 8 * 32; i += 256) {
        int i4 = i >> 5, l = i & 31, r0 = i4 * 4;
        float p3 = (r0 + 3 < 31) ? pw1[(r0 + 3) * 32 + l] : 0.0f;
        float f3 = (r0 + 3 < 31) ? fw1[(r0 + 3) * 32 + l] : 0.0f;
        s_pw1[i] = make_float4(pw1[r0 * 32 + l], pw1[(r0 + 1) * 32 + l],
                               pw1[(r0 + 2) * 32 + l], p3);
        s_fw1[i] = make_float4(fw1[r0 * 32 + l], fw1[(r0 + 1) * 32 + l],
                               fw1[(r0 + 2) * 32 + l], f3);
        s_pw2[i] = make_float4(pw2[r0 * 32 + l], pw2[(r0 + 1) * 32 + l],
                               pw2[(r0 + 2) * 32 + l], pw2[(r0 + 3) * 32 + l]);
        s_fw2[i] = make_float4(fw2[r0 * 32 + l], fw2[(r0 + 1) * 32 + l],
                               fw2[(r0 + 2) * 32 + l], fw2[(r0 + 3) * 32 + l]);
    }
    if (tid < 32) { s_pb1[tid] = pb1[tid]; s_pb2[tid] = pb2[tid];
                    s_fb1[tid] = fb1[tid]; s_fb2[tid] = fb2[tid]; }
    __syncthreads();

    int lane = tid & 31;
    int w    = tid >> 5;
    int pos0 = blockIdx.x * 32 + w * 4;
    int b    = blockIdx.x >> 6;
    int chunk = blockIdx.x & 63;

    float mk[4];
    #pragma unroll
    for (int q = 0; q < 4; q++) {
        int pos = pos0 + q;
        float t = times[pos], v = values[pos];
        mk[q] = mask[pos];
        int m = meas[pos];
        ((float*)&s_x4[w][q])[lane] = combined_lane(t, v, m, lane) * mk[q];
    }
    __syncwarp();

    float acc[4];

    // psi layer 1
    #pragma unroll
    for (int q = 0; q < 4; q++) acc[q] = s_pb1[lane];
    #pragma unroll
    for (int i4 = 0; i4 < 8; i4++) {
        float4 wv = s_pw1[i4 * 32 + lane];
        #pragma unroll
        for (int q = 0; q < 4; q++) {
            float4 xv = s_x4[w][q][i4];
            acc[q] += xv.x * wv.x; acc[q] += xv.y * wv.y;
            acc[q] += xv.z * wv.z; acc[q] += xv.w * wv.w;
        }
    }
    #pragma unroll
    for (int q = 0; q < 4; q++)
        ((float*)&s_h4[w][q])[lane] = fmaxf(acc[q], 0.0f) * mk[q];
    __syncwarp();

    // psi layer 2 (+ chunk partial)
    #pragma unroll
    for (int q = 0; q < 4; q++) acc[q] = s_pb2[lane];
    #pragma unroll
    for (int i4 = 0; i4 < 8; i4++) {
        float4 wv = s_pw2[i4 * 32 + lane];
        #pragma unroll
        for (int q = 0; q < 4; q++) {
            float4 xv = s_h4[w][q][i4];
            acc[q] += xv.x * wv.x; acc[q] += xv.y * wv.y;
            acc[q] += xv.z * wv.z; acc[q] += xv.w * wv.w;
        }
    }
    float psum = 0.0f;
    #pragma unroll
    for (int q = 0; q < 4; q++) {
        float ev = fmaxf(acc[q], 0.0f) * mk[q];
        g_enc_psi[(pos0 + q) * 32 + lane] = ev;
        psum += ev;
    }
    s_part[w][lane] = psum;
    __syncwarp();

    // phi layer 1
    #pragma unroll
    for (int q = 0; q < 4; q++) acc[q] = s_fb1[lane];
    #pragma unroll
    for (int i4 = 0; i4 < 8; i4++) {
        float4 wv = s_fw1[i4 * 32 + lane];
        #pragma unroll
        for (int q = 0; q < 4; q++) {
            float4 xv = s_x4[w][q][i4];
            acc[q] += xv.x * wv.x; acc[q] += xv.y * wv.y;
            acc[q] += xv.z * wv.z; acc[q] += xv.w * wv.w;
        }
    }
    #pragma unroll
    for (int q = 0; q < 4; q++)
        ((float*)&s_h4[w][q])[lane] = fmaxf(acc[q], 0.0f) * mk[q];
    __syncwarp();

    // phi layer 2
    #pragma unroll
    for (int q = 0; q < 4; q++) acc[q] = s_fb2[lane];
    #pragma unroll
    for (int i4 = 0; i4 < 8; i4++) {
        float4 wv = s_fw2[i4 * 32 + lane];
        #pragma unroll
        for (int q = 0; q < 4; q++) {
            float4 xv = s_h4[w][q][i4];
            acc[q] += xv.x * wv.x; acc[q] += xv.y * wv.y;
            acc[q] += xv.z * wv.z; acc[q] += xv.w * wv.w;
        }
    }
    #pragma unroll
    for (int q = 0; q < 4; q++)
        g_enc[(pos0 + q) * 32 + lane] = fmaxf(acc[q], 0.0f) * mk[q];

    // chunk total of enc_psi
    __syncthreads();
    if (w == 0) {
        float t = 0.0f;
        #pragma unroll
        for (int w2 = 0; w2 < 8; w2++) t += s_part[w2][lane];
        g_ct2[(b * NCHUNK + chunk) * 32 + lane] = t;
    }
}

// ---------------------------------------------------------------------------
// K3: inline aggraw (cumsum via g_ct2 chunk offsets + within-chunk prefix),
// agg matvec, keys matvec, preattn, u, and k45 chunk totals (u*enc, u).
// Grid 256 (block = chunk) x 256 threads.
// ---------------------------------------------------------------------------
__global__ __launch_bounds__(256) void k3_preattn(
    const float* __restrict__ times, const float* __restrict__ values,
    const int* __restrict__ meas, const float* __restrict__ mask,
    const float* __restrict__ arw, const float* __restrict__ arb,
    const float* __restrict__ wk, const float* __restrict__ wq)
{
    __shared__ float4 s_ar4[8 * 32];
    __shared__ float4 s_wk4[32 * 32];
    __shared__ float  s_ab[32], s_wq[64];
    __shared__ float4 s_g4[8][4][8];
    __shared__ float2 s_y2[8][4][32];
    __shared__ float  s_wp[8][32];
    __shared__ float  s_pn[8][4][32];
    __shared__ float  s_pd[8][4];

    int tid = threadIdx.x;
    for (int i = tid; i < 8 * 32; i += 256) {
        int i4 = i >> 5, l = i & 31, r0 = i4 * 4;
        s_ar4[i] = make_float4(arw[r0 * 32 + l], arw[(r0 + 1) * 32 + l],
                               arw[(r0 + 2) * 32 + l], arw[(r0 + 3) * 32 + l]);
    }
    for (int i = tid; i < 32 * 32; i += 256) {
        int i2 = i >> 5, l = i & 31, r0 = i2 * 2;
        float w2a = (r0 + 1 < 63) ? wk[(r0 + 1) * 64 + l]      : 0.0f;
        float w2b = (r0 + 1 < 63) ? wk[(r0 + 1) * 64 + l + 32] : 0.0f;
        s_wk4[i] = make_float4(wk[r0 * 64 + l], wk[r0 * 64 + l + 32], w2a, w2b);
    }
    if (tid < 32) s_ab[tid] = arb[tid];
    if (tid < 64) s_wq[tid] = wq[tid];

    int lane  = tid & 31;
    int w     = tid >> 5;
    int b     = blockIdx.x >> 6;
    int chunk = blockIdx.x & 63;
    int pos0  = blockIdx.x * 32 + w * 4;        // global position
    int lp0   = chunk * 32 + w * 4;             // LOCAL (within-sequence) position

    // Stage raw combined; load own-chunk enc_psi; within-warp prefix.
    float mk[4], cq[4];
    {
        float eq[4];
        #pragma unroll
        for (int q = 0; q < 4; q++) {
            int pos = pos0 + q;
            float t = times[pos], v = values[pos];
            mk[q] = mask[pos];
            int m = meas[pos];
            ((float*)s_y2[w][q])[lane] = combined_lane(t, v, m, lane);
            eq[q] = g_enc_psi[pos * 32 + lane];
        }
        cq[0] = eq[0];
        cq[1] = cq[0] + eq[1];
        cq[2] = cq[1] + eq[2];
        cq[3] = cq[2] + eq[3];
        s_wp[w][lane] = cq[3];
    }
    __syncthreads();   // covers weights, s_y2 low, s_wp

    // exclusive offset: preceding chunks (g_ct2) + preceding warps
    float off;
    {
        const float* ct = g_ct2 + (b * NCHUNK) * 32 + lane;
        float o0 = 0.f, o1 = 0.f, o2 = 0.f, o3 = 0.f;
        int k = 0;
        for (; k + 4 <= chunk; k += 4) {
            o0 += ct[k * 32];       o1 += ct[(k + 1) * 32];
            o2 += ct[(k + 2) * 32]; o3 += ct[(k + 3) * 32];
        }
        for (; k < chunk; k++) o0 += ct[k * 32];
        off = (o0 + o1) + (o2 + o3);
    }
    #pragma unroll
    for (int w2 = 0; w2 < 8; w2++)
        if (w2 < w) off += s_wp[w2][lane];

    // aggraw = cumsum / (LOCAL count) * mask -> staged for broadcast matvec
    #pragma unroll
    for (int q = 0; q < 4; q++) {
        float cum = off + cq[q];
        float agr = __fdividef(cum, (float)(lp0 + q + 1)) * mk[q];
        ((float*)&s_g4[w][q])[lane] = agr;
    }
    __syncwarp();

    // agg matvec (32x32)
    float agg[4];
    #pragma unroll
    for (int q = 0; q < 4; q++) agg[q] = s_ab[lane];
    #pragma unroll
    for (int i4 = 0; i4 < 8; i4++) {
        float4 wv = s_ar4[i4 * 32 + lane];
        #pragma unroll
        for (int q = 0; q < 4; q++) {
            float4 xv = s_g4[w][q][i4];
            agg[q] += xv.x * wv.x; agg[q] += xv.y * wv.y;
            agg[q] += xv.z * wv.z; agg[q] += xv.w * wv.w;
        }
    }
    #pragma unroll
    for (int q = 0; q < 4; q++) {
        ((float*)s_y2[w][q])[31 + lane] = agg[q] * mk[q];
        if (lane == 0) ((float*)s_y2[w][q])[63] = 0.0f;
    }
    __syncwarp();

    // keys matvec (63x64)
    float a0[4] = {0.f, 0.f, 0.f, 0.f}, a1[4] = {0.f, 0.f, 0.f, 0.f};
    #pragma unroll
    for (int i2 = 0; i2 < 32; i2++) {
        float4 wv = s_wk4[i2 * 32 + lane];
        #pragma unroll
        for (int q = 0; q < 4; q++) {
            float2 yv = s_y2[w][q][i2];
            a0[q] += yv.x * wv.x; a1[q] += yv.x * wv.y;
            a0[q] += yv.y * wv.z; a1[q] += yv.y * wv.w;
        }
    }

    int hh = lane & 3, dd = lane >> 2;
    float q0 = s_wq[hh * 16 + dd], q1 = s_wq[hh * 16 + dd + 8];
    float ufull[4];
    #pragma unroll
    for (int q = 0; q < 4; q++) {
        float part = a0[q] * mk[q] * q0 + a1[q] * mk[q] * q1;
        part += __shfl_xor_sync(FULL, part, 4);
        part += __shfl_xor_sync(FULL, part, 8);
        part += __shfl_xor_sync(FULL, part, 16);
        float pre = part * 0.25f * mk[q];
        ufull[q] = expf(pre);                    // lane l holds head l&3
        if (lane < 4) g_u[(pos0 + q) * 4 + lane] = ufull[q];
    }

    // k45 chunk totals: pn[h][lane] = sum_q u[q][h]*enc[q][lane]; pd[h] = sum_q u[q][h]
    {
        float e2q[4];
        #pragma unroll
        for (int q = 0; q < 4; q++) e2q[q] = g_enc[(pos0 + q) * 32 + lane];
        #pragma unroll
        for (int h = 0; h < 4; h++) {
            float s = 0.0f;
            #pragma unroll
            for (int q = 0; q < 4; q++)
                s += __shfl_sync(FULL, ufull[q], h) * e2q[q];
            s_pn[w][h][lane] = s;
        }
        if (lane < 4)
            s_pd[w][lane] = ufull[0] + ufull[1] + ufull[2] + ufull[3];
    }
    __syncthreads();

    if (w < 4) {
        int h = w;
        float t = 0.0f;
        #pragma unroll
        for (int w2 = 0; w2 < 8; w2++) t += s_pn[w2][h][lane];
        g_ct4n[((b * 4 + h) * NCHUNK + chunk) * 32 + lane] = t;
        if (lane == 0) {
            float td = 0.0f;
            #pragma unroll
            for (int w2 = 0; w2 < 8; w2++) td += s_pd[w2][h];
            g_ct4d[(b * 4 + h) * NCHUNK + chunk] = td;
        }
    }
}

// ---------------------------------------------------------------------------
// K45: fused scan + rho MLP. Grid 256 (block = chunk of 32 positions) x 512
// threads (16 warps), 2 blocks/SM co-resident (single wave, ~28 warps/SM).
// Phase 0: warps 0-3 = per-head causal scans (offsets from chunk totals +
//          register chain), writing num*mask^2/den DIRECTLY into s_a (no
//          g_num/g_den round trip). Warps 4-15 stage the 48KB rho weights.
// Phase 1: all 16 warps run the R12 k5 math, Q=2 positions/warp.
// smem: s_w1 32KB + s_w2 16KB + s_a 16KB + s_h 8KB = 72KB.
// ---------------------------------------------------------------------------
__global__ __launch_bounds__(512, 2) void k45_fused(
    const float* __restrict__ mask,
    const float* __restrict__ rw1, const float* __restrict__ rb1,
    const float* __restrict__ rw2, const float* __restrict__ rb2,
    float* __restrict__ out)
{
    extern __shared__ char sm[];
    float4* s_w1 = (float4*)sm;                  // 2048 float4 = 32KB
    float4* s_w2 = (float4*)(sm + 32768);        // 1024 float4 = 16KB
    float*  s_a  = (float*) (sm + 49152);        // 32*128 fl   = 16KB
    float*  s_h  = (float*) (sm + 65536);        // 32*64 fl    =  8KB

    int tid  = threadIdx.x;
    int w    = tid >> 5, lane = tid & 31;
    int b    = blockIdx.x >> 6;
    int chunk = blockIdx.x & 63;
    int p0   = chunk * 32;                       // local position base

    if (w >= 4) {
        // ---- Phase 0b: stage weights (threads 128..511) ----
        int t = tid - 128;
        for (int i = t; i < 2048; i += 384) {
            int kp = i >> 5, l = i & 31, k = kp * 2;
            s_w1[i] = make_float4(rw1[k * 64 + l],       rw1[k * 64 + l + 32],
                                  rw1[(k + 1) * 64 + l], rw1[(k + 1) * 64 + l + 32]);
        }
        for (int i = t; i < 1024; i += 384) {
            int kp = i >> 5, l = i & 31, k = kp * 2;
            s_w2[i] = make_float4(rw2[k * 64 + l],       rw2[k * 64 + l + 32],
                                  rw2[(k + 1) * 64 + l], rw2[(k + 1) * 64 + l + 32]);
        }
    } else {
        // ---- Phase 0a: per-head causal scan (warp w = head h) ----
        int h  = w;
        int bh = b * 4 + h;

        // num offset from chunk totals (coalesced)
        float accn;
        {
            const float* ct = g_ct4n + (bh * NCHUNK) * 32 + lane;
            float o0 = 0.f, o1 = 0.f, o2 = 0.f, o3 = 0.f;
            int k = 0;
            for (; k + 4 <= chunk; k += 4) {
                o0 += ct[k * 32];       o1 += ct[(k + 1) * 32];
                o2 += ct[(k + 2) * 32]; o3 += ct[(k + 3) * 32];
            }
            for (; k < chunk; k++) o0 += ct[k * 32];
            accn = (o0 + o1) + (o2 + o3);
        }
        // den offset
        float accu;
        {
            const float* cd = g_ct4d + bh * NCHUNK;
            float myd = 0.0f;
            if (lane < chunk)      myd  = cd[lane];
            if (lane + 32 < chunk) myd += cd[lane + 32];
            #pragma unroll
            for (int o = 16; o >= 1; o >>= 1) myd += __shfl_xor_sync(FULL, myd, o);
            accu = myd;
        }

        const float* up = g_u   + b * P_ * 4 + h;
        const float* ep = g_enc + b * P_ * 32 + lane;
        const float* mp = mask  + b * P_;

        // 4 tiles of 8 positions (keeps regs under 63 for 2-block residency)
        #pragma unroll
        for (int tile = 0; tile < 4; tile++) {
            int base = p0 + tile * 8;
            float uu[8], ee[8], mm[8];
            #pragma unroll
            for (int j = 0; j < 8; j++) {
                uu[j] = up[(base + j) * 4];
                ee[j] = ep[(base + j) * 32];
                mm[j] = mp[base + j];
            }
            #pragma unroll
            for (int j = 0; j < 8; j++) {
                accn += uu[j] * ee[j];
                accu += uu[j];
                float sc = __fdividef(mm[j] * mm[j], accu);
                s_a[(tile * 8 + j) * 128 + h * 32 + lane] = accn * sc;
            }
        }
    }
    __syncthreads();

    // ---- Phase 1: rho MLP, Q=2 positions per warp ----
    int pl0 = w * 2;                      // local positions pl0, pl0+1
    int gp0 = b * P_ + p0 + pl0;
    float mks[2] = { mask[gp0], mask[gp0 + 1] };
    const float4* s_a4 = (const float4*)s_a;

    float acc0[2], acc1[2];
    {
        float b0 = rb1[lane], b1v = rb1[lane + 32];
        acc0[0] = b0;  acc0[1] = b0;
        acc1[0] = b1v; acc1[1] = b1v;
    }

    #pragma unroll 4
    for (int g = 0; g < 32; g++) {                   // 4 k's per group
        float4 wa = s_w1[(2 * g) * 32 + lane];       // k=4g, 4g+1
        float4 wb = s_w1[(2 * g + 1) * 32 + lane];   // k=4g+2, 4g+3
        #pragma unroll
        for (int q = 0; q < 2; q++) {
            float4 av = s_a4[(pl0 + q) * 32 + g];    // broadcast
            acc0[q] += av.x * wa.x; acc1[q] += av.x * wa.y;
            acc0[q] += av.y * wa.z; acc1[q] += av.y * wa.w;
            acc0[q] += av.z * wb.x; acc1[q] += av.z * wb.y;
            acc0[q] += av.w * wb.z; acc1[q] += av.w * wb.w;
        }
    }

    // relu + mask -> s_h
    #pragma unroll
    for (int q = 0; q < 2; q++) {
        float* hp = s_h + (pl0 + q) * 64;
        hp[lane]      = fmaxf(acc0[q], 0.0f) * mks[q];
        hp[lane + 32] = fmaxf(acc1[q], 0.0f) * mks[q];
    }
    __syncwarp();

    // ---- layer 2 ----
    {
        float b0 = rb2[lane], b1v = rb2[lane + 32];
        acc0[0] = b0;  acc0[1] = b0;
        acc1[0] = b1v; acc1[1] = b1v;
    }

    #pragma unroll 4
    for (int g = 0; g < 16; g++) {
        float4 wa = s_w2[(2 * g) * 32 + lane];
        float4 wb = s_w2[(2 * g + 1) * 32 + lane];
        #pragma unroll
        for (int q = 0; q < 2; q++) {
            float4 av = *(const float4*)(s_h + (pl0 + q) * 64 + 4 * g);  // bcast
            acc0[q] += av.x * wa.x; acc1[q] += av.x * wa.y;
            acc0[q] += av.y * wa.z; acc1[q] += av.y * wa.w;
            acc0[q] += av.z * wb.x; acc1[q] += av.z * wb.y;
            acc0[q] += av.w * wb.z; acc1[q] += av.w * wb.w;
        }
    }

    // relu + mask -> output
    #pragma unroll
    for (int q = 0; q < 2; q++) {
        int gpos = gp0 + q;
        out[gpos * 64 + lane]      = fmaxf(acc0[q], 0.0f) * mks[q];
        out[gpos * 64 + lane + 32] = fmaxf(acc1[q], 0.0f) * mks[q];
    }
}

// ---------------------------------------------------------------------------
extern "C" void kernel_launch(void* const* d_in, const int* in_sizes, int n_in,
                              void* d_out, int out_size)
{
    const float* times   = (const float*)d_in[0];
    const float* values  = (const float*)d_in[1];
    const int*   meas    = (const int*)  d_in[2];
    const float* mask    = (const float*)d_in[3];
    const float* psi_w1  = (const float*)d_in[4];
    const float* psi_b1  = (const float*)d_in[5];
    const float* psi_w2  = (const float*)d_in[6];
    const float* psi_b2  = (const float*)d_in[7];
    const float* arho_w  = (const float*)d_in[8];
    const float* arho_b  = (const float*)d_in[9];
    const float* W_k     = (const float*)d_in[10];
    const float* W_q     = (const float*)d_in[11];
    const float* phi_w1  = (const float*)d_in[12];
    const float* phi_b1  = (const float*)d_in[13];
    const float* phi_w2  = (const float*)d_in[14];
    const float* phi_b2  = (const float*)d_in[15];
    const float* rho_w1  = (const float*)d_in[16];
    const float* rho_b1  = (const float*)d_in[17];
    const float* rho_w2  = (const float*)d_in[18];
    const float* rho_b2  = (const float*)d_in[19];
    float* out = (float*)d_out;

    cudaFuncSetAttribute(k45_fused, cudaFuncAttributeMaxDynamicSharedMemorySize, 73728);

    k1_feat_mlps<<<256, 256>>>(times, values, meas, mask,
                               psi_w1, psi_b1, psi_w2, psi_b2,
                               phi_w1, phi_b1, phi_w2, phi_b2);
    k3_preattn<<<256, 256>>>(times, values, meas, mask,
                             arho_w, arho_b, W_k, W_q);
    k45_fused<<<256, 512, 73728>>>(mask, rho_w1, rho_b1, rho_w2, rho_b2, out);
}